// round 1
// baseline (speedup 1.0000x reference)
#include <cuda_runtime.h>
#include <cstdint>

// ---------------------------------------------------------------------------
// Problem constants: B=1, T=256, D=512, H=8, DH=64
// proj layout: [t, 5*512]; chunks k1@0, k2@512, q@1024, v1@1536, v2@2048,
// per head columns h*64..h*64+63 inside each chunk.
// ---------------------------------------------------------------------------
#define T 256
#define D 512
#define H 8
#define DH 64

// Scratch (device globals — allocation-free rule)
__device__ float g_proj[T * 5 * D];                           // 256 x 2560
__device__ float g_K1W[(long long)H * T * DH * DH];           // [h][p][j*64+i]
__device__ float g_Vq1[(long long)H * T * DH * DH];           // [h][p][c*64+e]
__device__ float g_S[(long long)H * T * T * DH];              // [h][p][q][j]
__device__ float g_attn[(long long)H * T * T * T];            // [h][p][q][t]  (134M floats)
__device__ float g_A2[(long long)H * T * T * DH];             // [h][q][p][c]
__device__ float g_rowmax[H * T];
__device__ float g_rowinv[H * T];
__device__ float g_z[T * H * DH];                             // [q][h*64+e]

// ---------------------------------------------------------------------------
// Generic batched tiled GEMM: C[m,n] = sum_k A[m,k] * B(k,n)
//   batch index b -> h = b/P, p = b%P; pointer offsets h*xH + p*xP (elements)
//   transB: B indexed [n*ldb + k]
//   mode 1: causal tile skip (attn logits):  skip if qmax<p or tmin>qmax
//   mode 2: k-limit (A2):  k_end = min(K, m0+64); zero if qmax<p
//   ksplit>1: split-K with atomicAdd epilogue
//   rowscale: per-row scale (index h*rsH + m)
// All M,N multiples of 64; all K ranges multiples of 16 (asserted by usage).
// ---------------------------------------------------------------------------
__global__ void gemm_kernel(const float* __restrict__ A, const float* __restrict__ Bm,
                            float* __restrict__ C,
                            int lda, int ldb, int ldc,
                            int M, int N, int K, int P,
                            long long aH, long long aP,
                            long long bH, long long bP,
                            long long cH, long long cP,
                            int transB,
                            const float* __restrict__ bias,
                            const float* __restrict__ rowscale, int rsH,
                            int mode, int ksplit)
{
    int bz = blockIdx.z;
    int b  = bz / ksplit;
    int kc = bz % ksplit;
    int h = b / P, p = b % P;
    A  += (long long)h * aH + (long long)p * aP;
    Bm += (long long)h * bH + (long long)p * bP;
    C  += (long long)h * cH + (long long)p * cP;

    int m0 = blockIdx.y * 64;
    int n0 = blockIdx.x * 64;

    int k_begin = 0, k_end = K;
    if (ksplit > 1) { int kchunk = K / ksplit; k_begin = kc * kchunk; k_end = k_begin + kchunk; }
    if (mode == 1) { if (m0 + 63 < p || n0 > m0 + 63) return; }
    if (mode == 2) {
        if (m0 + 63 < p) k_end = k_begin;                 // whole tile below diagonal -> zeros
        else { int lim = m0 + 64; if (lim < k_end) k_end = lim; }
    }

    __shared__ float As[16][65];
    __shared__ float Bs[16][65];

    int tid = threadIdx.x;
    int ty = tid >> 4, tx = tid & 15;

    float acc[4][4] = {};

    for (int k0 = k_begin; k0 < k_end; k0 += 16) {
        // load A tile (64 rows x 16 k), stored transposed As[k][m]
        #pragma unroll
        for (int i = tid; i < 64 * 16; i += 256) {
            int r = i >> 4, kk = i & 15;
            As[kk][r] = A[(long long)(m0 + r) * lda + (k0 + kk)];
        }
        if (transB) {
            #pragma unroll
            for (int i = tid; i < 64 * 16; i += 256) {
                int n = i >> 4, kk = i & 15;
                Bs[kk][n] = Bm[(long long)(n0 + n) * ldb + (k0 + kk)];
            }
        } else {
            #pragma unroll
            for (int i = tid; i < 16 * 64; i += 256) {
                int kk = i >> 6, n = i & 63;
                Bs[kk][n] = Bm[(long long)(k0 + kk) * ldb + (n0 + n)];
            }
        }
        __syncthreads();

        #pragma unroll
        for (int kk = 0; kk < 16; kk++) {
            float a[4], bv[4];
            #pragma unroll
            for (int i = 0; i < 4; i++) a[i] = As[kk][ty * 4 + i];
            #pragma unroll
            for (int j = 0; j < 4; j++) bv[j] = Bs[kk][tx * 4 + j];
            #pragma unroll
            for (int i = 0; i < 4; i++)
                #pragma unroll
                for (int j = 0; j < 4; j++)
                    acc[i][j] += a[i] * bv[j];
        }
        __syncthreads();
    }

    #pragma unroll
    for (int i = 0; i < 4; i++) {
        int m = m0 + ty * 4 + i;
        float scale = rowscale ? rowscale[h * rsH + m] : 1.0f;
        #pragma unroll
        for (int j = 0; j < 4; j++) {
            int n = n0 + tx * 4 + j;
            float v = acc[i][j] * scale;
            if (bias) v += bias[n];
            if (ksplit > 1) atomicAdd(&C[(long long)m * ldc + n], v);
            else            C[(long long)m * ldc + n] = v;
        }
    }
}

// ---------------------------------------------------------------------------
// Row stats: for each (h,q) compute max and 1/sum of exp(logit/DH - max) over
// the valid region p<=q, t<=q. Online softmax per-thread, then block combine.
// grid = (T, H), block = 256
// ---------------------------------------------------------------------------
__global__ void rowstats_kernel(const float* __restrict__ attn,
                                float* __restrict__ rowmax,
                                float* __restrict__ rowinv)
{
    int q = blockIdx.x, h = blockIdx.y;
    int tid = threadIdx.x;
    const float inv = 1.0f / (float)DH;

    float m = -1e30f, s = 0.0f;
    for (int p = 0; p <= q; p++) {
        const float* row = attn + (((long long)h * T + p) * T + q) * T;
        for (int t = tid; t <= q; t += 256) {
            float x = row[t] * inv;
            if (x > m) { s *= __expf(m - x); m = x; }
            s += __expf(x - m);
        }
    }

    __shared__ float sm[256], ss[256];
    sm[tid] = m; ss[tid] = s;
    __syncthreads();
    for (int o = 128; o > 0; o >>= 1) {
        if (tid < o) {
            float m2 = sm[tid + o], s2 = ss[tid + o];
            float M = fmaxf(sm[tid], m2);
            ss[tid] = ss[tid] * __expf(sm[tid] - M) + s2 * __expf(m2 - M);
            sm[tid] = M;
        }
        __syncthreads();
    }
    if (tid == 0) {
        rowmax[h * T + q] = sm[0];
        rowinv[h * T + q] = 1.0f / ss[0];
    }
}

// ---------------------------------------------------------------------------
// Exp + mask writeback over the full [h][p][q][t] cube.
// ---------------------------------------------------------------------------
__global__ void expmask_kernel(float* __restrict__ attn,
                               const float* __restrict__ rowmax)
{
    long long idx = (long long)blockIdx.x * 256 + threadIdx.x;
    const float inv = 1.0f / (float)DH;
    int t = (int)(idx & 255);
    long long r = idx >> 8;
    int q = (int)(r & 255); r >>= 8;
    int p = (int)(r & 255);
    int h = (int)(r >> 8);
    float v = 0.0f;
    if (p <= q && t <= q)
        v = __expf(attn[idx] * inv - rowmax[h * T + q]);
    attn[idx] = v;
}

// ---------------------------------------------------------------------------
static inline void launch_gemm(const float* A, long long aH, long long aP, int lda,
                               const float* B, long long bH, long long bP, int ldb,
                               float* C, long long cH, long long cP, int ldc,
                               int M, int N, int K, int P, int batch,
                               int transB, const float* bias,
                               const float* rowscale, int rsH,
                               int mode, int ksplit)
{
    dim3 grid(N / 64, M / 64, batch * ksplit);
    gemm_kernel<<<grid, 256>>>(A, B, C, lda, ldb, ldc, M, N, K, P,
                               aH, aP, bH, bP, cH, cP,
                               transB, bias, rowscale, rsH, mode, ksplit);
}

extern "C" void kernel_launch(void* const* d_in, const int* in_sizes, int n_in,
                              void* d_out, int out_size)
{
    const float* x    = (const float*)d_in[0];   // [256, 512]
    const float* Wk   = (const float*)d_in[1];   // [512, 2560]
    const float* bk   = (const float*)d_in[2];   // [2560]
    const float* WKq  = (const float*)d_in[3];   // [8,64,64,64]
    const float* WVq  = (const float*)d_in[4];   // [8,64,64,64]
    const float* Wout = (const float*)d_in[5];   // [512, 512]
    const float* bout = (const float*)d_in[6];   // [512]
    float* out = (float*)d_out;                  // [256, 512]

    float *proj, *k1w, *vq1, *S, *attn, *A2, *rmax, *rinv, *z;
    cudaGetSymbolAddress((void**)&proj, g_proj);
    cudaGetSymbolAddress((void**)&k1w,  g_K1W);
    cudaGetSymbolAddress((void**)&vq1,  g_Vq1);
    cudaGetSymbolAddress((void**)&S,    g_S);
    cudaGetSymbolAddress((void**)&attn, g_attn);
    cudaGetSymbolAddress((void**)&A2,   g_A2);
    cudaGetSymbolAddress((void**)&rmax, g_rowmax);
    cudaGetSymbolAddress((void**)&rinv, g_rowinv);
    cudaGetSymbolAddress((void**)&z,    g_z);

    const long long HPJ = (long long)T * DH * DH;     // 1048576 per-head K1W/Vq1
    const long long SH  = (long long)T * T * DH;      // 4194304 per-head S / A2
    const long long AH  = (long long)T * T * T;       // 16777216 per-head attn

    // 1) proj = x @ W_kkqvv + b        [256,2560] = [256,512]x[512,2560]
    launch_gemm(x, 0, 0, D, Wk, 0, 0, 5 * D, proj, 0, 0, 5 * D,
                T, 5 * D, D, 1, 1, 0, bk, nullptr, 0, 0, 1);

    // 2) K1W[h] = k1_h @ W_Kq[h]      batch 8: [256,4096] = [256,64]x[64,4096]
    launch_gemm(proj + 0, 64, 0, 5 * D, WKq, (long long)DH * DH * DH, 0, DH * DH,
                k1w, HPJ, 0, DH * DH,
                T, DH * DH, DH, 1, H, 0, nullptr, nullptr, 0, 0, 1);

    // 3) Vq1[h] = v1_h @ W_Vq[h]
    launch_gemm(proj + 3 * D, 64, 0, 5 * D, WVq, (long long)DH * DH * DH, 0, DH * DH,
                vq1, HPJ, 0, DH * DH,
                T, DH * DH, DH, 1, H, 0, nullptr, nullptr, 0, 0, 1);

    // 4) S[h][p][q][j] = q_h[q,i] * K1W[h][p][j,i]   batch 2048 (h,p), transB
    launch_gemm(proj + 2 * D, 64, 0, 5 * D,
                k1w, HPJ, DH * DH, DH,
                S, SH, (long long)T * DH, DH,
                T, DH, DH, T, H * T, 1, nullptr, nullptr, 0, 0, 1);

    // 5) logits[h][p][q][t] = S[h][p][q,j] * k2_h[t,j]   batch 2048, transB, causal skip
    launch_gemm(S, SH, (long long)T * DH, DH,
                proj + 1 * D, 64, 0, 5 * D,
                attn, AH, (long long)T * T, T,
                T, T, DH, T, H * T, 1, nullptr, nullptr, 0, 1, 1);

    // 6) row stats (max, 1/sum)
    {
        dim3 grid(T, H);
        rowstats_kernel<<<grid, 256>>>(attn, rmax, rinv);
    }

    // 7) exp + mask writeback (full cube)
    {
        long long total = (long long)H * T * T * T;
        int blocks = (int)(total / 256);
        expmask_kernel<<<blocks, 256>>>(attn, rmax);
    }

    // 8) A2[h][q][p][c] = expA[h][p][q,t] * v2_h[t,c]   batch 2048, k-limited
    launch_gemm(attn, AH, (long long)T * T, T,
                proj + 4 * D, 64, 0, 5 * D,
                A2, SH, DH, T * DH,
                T, DH, T, T, H * T, 0, nullptr, nullptr, 0, 2, 1);

    // 9) z[q][h*64+e] = rowinv[h,q] * sum_{p,c} A2[h][q][p*64+c] * Vq1[h][(p*64+c)][e]
    cudaMemsetAsync(z, 0, (size_t)T * H * DH * sizeof(float));
    launch_gemm(A2, SH, 0, T * DH,
                vq1, HPJ, 0, DH,
                z, DH, 0, H * DH,
                T, DH, T * DH, 1, H, 0, nullptr, rinv, T, 0, 16);

    // 10) out = z @ W_out + b_out     [256,512] = [256,512]x[512,512]
    launch_gemm(z, 0, 0, H * DH, Wout, 0, 0, D,
                out, 0, 0, D,
                T, D, H * DH, 1, 1, 0, bout, nullptr, 0, 0, 1);
}

// round 2
// speedup vs baseline: 1.2368x; 1.2368x over previous
#include <cuda_runtime.h>
#include <cstdint>

// ---------------------------------------------------------------------------
// Problem constants: B=1, T=256, D=512, H=8, DH=64
// proj layout: [t, 5*512]; chunks k1@0, k2@512, q@1024, v1@1536, v2@2048,
// per head columns h*64..h*64+63 inside each chunk.
// ---------------------------------------------------------------------------
#define T 256
#define D 512
#define H 8
#define DH 64

// Scratch (device globals — allocation-free rule)
__device__ float g_proj[T * 5 * D];                           // 256 x 2560
__device__ float g_K1W[(long long)H * T * DH * DH];           // [h][p][j*64+i]
__device__ float g_Vq1[(long long)H * T * DH * DH];           // [h][p][c*64+e]
__device__ float g_attn[(long long)H * T * T * T];            // [h][p][q][t] logits
__device__ float g_A2[(long long)H * T * T * DH];             // [h][q][p*64+c]
__device__ float g_rowmax[H * T];
__device__ float g_rowinv[H * T];
__device__ float g_z[T * H * DH];                             // [q][h*64+e]

// ---------------------------------------------------------------------------
// Generic batched tiled GEMM: C[m,n] = sum_k A[m,k] * B(k,n)
//   batch index b -> h = b/P, p = b%P; pointer offsets h*xH + p*xP (elements)
//   transB: B indexed [n*ldb + k]
//   mode 3 (A2 step): A is the logits cube slice [q][t]; apply
//     w = (p<=q && t<=q) ? exp(a/64 - rowmax[h,q]) : 0 on A-load,
//     and k_end = min(K, m0+64); if tile fully below diagonal -> zeros.
//   ksplit>1: split-K with atomicAdd epilogue
//   rowscale: per-row scale (index h*rsH + m)
// ---------------------------------------------------------------------------
__global__ void gemm_kernel(const float* __restrict__ A, const float* __restrict__ Bm,
                            float* __restrict__ C,
                            int lda, int ldb, int ldc,
                            int M, int N, int K, int P,
                            long long aH, long long aP,
                            long long bH, long long bP,
                            long long cH, long long cP,
                            int transB,
                            const float* __restrict__ bias,
                            const float* __restrict__ rowscale, int rsH,
                            const float* __restrict__ rowmax,
                            int mode, int ksplit)
{
    int bz = blockIdx.z;
    int b  = bz / ksplit;
    int kc = bz % ksplit;
    int h = b / P, p = b % P;
    A  += (long long)h * aH + (long long)p * aP;
    Bm += (long long)h * bH + (long long)p * bP;
    C  += (long long)h * cH + (long long)p * cP;

    int m0 = blockIdx.y * 64;
    int n0 = blockIdx.x * 64;

    int k_begin = 0, k_end = K;
    if (ksplit > 1) { int kchunk = K / ksplit; k_begin = kc * kchunk; k_end = k_begin + kchunk; }
    if (mode == 3) {
        if (m0 + 63 < p) k_end = k_begin;                 // whole tile below diagonal -> zeros
        else { int lim = m0 + 64; if (lim < k_end) k_end = lim; }
    }

    __shared__ float As[16][65];
    __shared__ float Bs[16][65];

    int tid = threadIdx.x;
    int ty = tid >> 4, tx = tid & 15;

    float acc[4][4] = {};

    for (int k0 = k_begin; k0 < k_end; k0 += 16) {
        if (mode == 3) {
            #pragma unroll
            for (int i = tid; i < 64 * 16; i += 256) {
                int r = i >> 4, kk = i & 15;
                int qg = m0 + r, tg = k0 + kk;
                float w = 0.0f;
                if (p <= qg && tg <= qg) {
                    float a = A[(long long)qg * lda + tg];
                    w = __expf(a * 0.015625f - rowmax[h * T + qg]);
                }
                As[kk][r] = w;
            }
        } else {
            #pragma unroll
            for (int i = tid; i < 64 * 16; i += 256) {
                int r = i >> 4, kk = i & 15;
                As[kk][r] = A[(long long)(m0 + r) * lda + (k0 + kk)];
            }
        }
        if (transB) {
            #pragma unroll
            for (int i = tid; i < 64 * 16; i += 256) {
                int n = i >> 4, kk = i & 15;
                Bs[kk][n] = Bm[(long long)(n0 + n) * ldb + (k0 + kk)];
            }
        } else {
            #pragma unroll
            for (int i = tid; i < 16 * 64; i += 256) {
                int kk = i >> 6, n = i & 63;
                Bs[kk][n] = Bm[(long long)(k0 + kk) * ldb + (n0 + n)];
            }
        }
        __syncthreads();

        #pragma unroll
        for (int kk = 0; kk < 16; kk++) {
            float a[4], bv[4];
            #pragma unroll
            for (int i = 0; i < 4; i++) a[i] = As[kk][ty * 4 + i];
            #pragma unroll
            for (int j = 0; j < 4; j++) bv[j] = Bs[kk][tx * 4 + j];
            #pragma unroll
            for (int i = 0; i < 4; i++)
                #pragma unroll
                for (int j = 0; j < 4; j++)
                    acc[i][j] += a[i] * bv[j];
        }
        __syncthreads();
    }

    #pragma unroll
    for (int i = 0; i < 4; i++) {
        int m = m0 + ty * 4 + i;
        float scale = rowscale ? rowscale[h * rsH + m] : 1.0f;
        #pragma unroll
        for (int j = 0; j < 4; j++) {
            int n = n0 + tx * 4 + j;
            float v = acc[i][j] * scale;
            if (bias) v += bias[n];
            if (ksplit > 1) atomicAdd(&C[(long long)m * ldc + n], v);
            else            C[(long long)m * ldc + n] = v;
        }
    }
}

// ---------------------------------------------------------------------------
// Fused steps 4+5: per (h, p, qtile) compute
//   St[j][q] = sum_i q_h[q,i] * K1W[h][p][j*64+i]   (64x64, kept in smem, transposed)
//   logits[h][p][q][t] = sum_j St[j][q] * k2_h[t,j]  for t-tiles tt <= qtile
// grid = (qtile=4, p=256, h=8), block = 256
// ---------------------------------------------------------------------------
__global__ void logits_kernel(const float* __restrict__ proj,
                              const float* __restrict__ k1w,
                              float* __restrict__ attn)
{
    int qt = blockIdx.x;
    int p  = blockIdx.y;
    int h  = blockIdx.z;
    if (qt * 64 + 63 < p) return;                        // causal tile skip

    const float* qmat = proj + 2 * D + h * 64;           // [q][i], ld = 5*D
    const float* k2m  = proj + 1 * D + h * 64;           // [t][j], ld = 5*D
    const float* Bp   = k1w + ((long long)h * T + p) * (DH * DH);  // [j*64+i]
    float* Cb = attn + ((long long)(h * T + p)) * T * T; // [q][t], ld = T

    __shared__ float As[16][65];
    __shared__ float Bs[16][65];
    __shared__ float St[64][65];                         // St[j][q]

    int tid = threadIdx.x;
    int ty = tid >> 4, tx = tid & 15;
    int q0 = qt * 64;

    // Phase 1: St = q-tile @ K1W[p]^T  (rows q, cols j, contract i)
    {
        float acc[4][4] = {};
        for (int k0 = 0; k0 < 64; k0 += 16) {
            #pragma unroll
            for (int i = tid; i < 64 * 16; i += 256) {
                int r = i >> 4, kk = i & 15;
                As[kk][r] = qmat[(long long)(q0 + r) * (5 * D) + (k0 + kk)];
            }
            #pragma unroll
            for (int i = tid; i < 64 * 16; i += 256) {
                int n = i >> 4, kk = i & 15;          // n = j
                Bs[kk][n] = Bp[n * 64 + (k0 + kk)];
            }
            __syncthreads();
            #pragma unroll
            for (int kk = 0; kk < 16; kk++) {
                float a[4], bv[4];
                #pragma unroll
                for (int i = 0; i < 4; i++) a[i] = As[kk][ty * 4 + i];
                #pragma unroll
                for (int j = 0; j < 4; j++) bv[j] = Bs[kk][tx * 4 + j];
                #pragma unroll
                for (int i = 0; i < 4; i++)
                    #pragma unroll
                    for (int j = 0; j < 4; j++)
                        acc[i][j] += a[i] * bv[j];
            }
            __syncthreads();
        }
        // store transposed: St[j][q]
        #pragma unroll
        for (int i = 0; i < 4; i++)
            #pragma unroll
            for (int j = 0; j < 4; j++)
                St[tx * 4 + j][ty * 4 + i] = acc[i][j];
    }
    __syncthreads();

    // Phase 2: for each t-tile <= qt: L = St^T @ k2^T  (rows q, cols t, contract j)
    for (int tt = 0; tt <= qt; tt++) {
        int t0 = tt * 64;
        float acc[4][4] = {};
        for (int j0 = 0; j0 < 64; j0 += 16) {
            #pragma unroll
            for (int i = tid; i < 64 * 16; i += 256) {
                int n = i >> 4, kk = i & 15;          // n = t
                Bs[kk][n] = k2m[(long long)(t0 + n) * (5 * D) + (j0 + kk)];
            }
            __syncthreads();
            #pragma unroll
            for (int kk = 0; kk < 16; kk++) {
                float a[4], bv[4];
                #pragma unroll
                for (int i = 0; i < 4; i++) a[i] = St[j0 + kk][ty * 4 + i];
                #pragma unroll
                for (int j = 0; j < 4; j++) bv[j] = Bs[kk][tx * 4 + j];
                #pragma unroll
                for (int i = 0; i < 4; i++)
                    #pragma unroll
                    for (int j = 0; j < 4; j++)
                        acc[i][j] += a[i] * bv[j];
            }
            __syncthreads();
        }
        #pragma unroll
        for (int i = 0; i < 4; i++) {
            int q = q0 + ty * 4 + i;
            #pragma unroll
            for (int j = 0; j < 4; j++) {
                int t = t0 + tx * 4 + j;
                Cb[(long long)q * T + t] = acc[i][j];
            }
        }
    }
}

// ---------------------------------------------------------------------------
// Row stats: for each (h,q) compute max and 1/sum of exp(logit/DH - max) over
// the valid region p<=q, t<=q.
// ---------------------------------------------------------------------------
__global__ void rowstats_kernel(const float* __restrict__ attn,
                                float* __restrict__ rowmax,
                                float* __restrict__ rowinv)
{
    int q = blockIdx.x, h = blockIdx.y;
    int tid = threadIdx.x;
    const float inv = 1.0f / (float)DH;

    float m = -1e30f, s = 0.0f;
    for (int p = 0; p <= q; p++) {
        const float* row = attn + (((long long)h * T + p) * T + q) * T;
        for (int t = tid; t <= q; t += 256) {
            float x = row[t] * inv;
            if (x > m) { s *= __expf(m - x); m = x; }
            s += __expf(x - m);
        }
    }

    __shared__ float sm[256], ss[256];
    sm[tid] = m; ss[tid] = s;
    __syncthreads();
    for (int o = 128; o > 0; o >>= 1) {
        if (tid < o) {
            float m2 = sm[tid + o], s2 = ss[tid + o];
            float M = fmaxf(sm[tid], m2);
            ss[tid] = ss[tid] * __expf(sm[tid] - M) + s2 * __expf(m2 - M);
            sm[tid] = M;
        }
        __syncthreads();
    }
    if (tid == 0) {
        rowmax[h * T + q] = sm[0];
        rowinv[h * T + q] = 1.0f / ss[0];
    }
}

// ---------------------------------------------------------------------------
static inline void launch_gemm(const float* A, long long aH, long long aP, int lda,
                               const float* B, long long bH, long long bP, int ldb,
                               float* C, long long cH, long long cP, int ldc,
                               int M, int N, int K, int P, int batch,
                               int transB, const float* bias,
                               const float* rowscale, int rsH,
                               const float* rowmax,
                               int mode, int ksplit)
{
    dim3 grid(N / 64, M / 64, batch * ksplit);
    gemm_kernel<<<grid, 256>>>(A, B, C, lda, ldb, ldc, M, N, K, P,
                               aH, aP, bH, bP, cH, cP,
                               transB, bias, rowscale, rsH, rowmax, mode, ksplit);
}

extern "C" void kernel_launch(void* const* d_in, const int* in_sizes, int n_in,
                              void* d_out, int out_size)
{
    const float* x    = (const float*)d_in[0];   // [256, 512]
    const float* Wk   = (const float*)d_in[1];   // [512, 2560]
    const float* bk   = (const float*)d_in[2];   // [2560]
    const float* WKq  = (const float*)d_in[3];   // [8,64,64,64]
    const float* WVq  = (const float*)d_in[4];   // [8,64,64,64]
    const float* Wout = (const float*)d_in[5];   // [512, 512]
    const float* bout = (const float*)d_in[6];   // [512]
    float* out = (float*)d_out;                  // [256, 512]

    float *proj, *k1w, *vq1, *attn, *A2, *rmax, *rinv, *z;
    cudaGetSymbolAddress((void**)&proj, g_proj);
    cudaGetSymbolAddress((void**)&k1w,  g_K1W);
    cudaGetSymbolAddress((void**)&vq1,  g_Vq1);
    cudaGetSymbolAddress((void**)&attn, g_attn);
    cudaGetSymbolAddress((void**)&A2,   g_A2);
    cudaGetSymbolAddress((void**)&rmax, g_rowmax);
    cudaGetSymbolAddress((void**)&rinv, g_rowinv);
    cudaGetSymbolAddress((void**)&z,    g_z);

    const long long HPJ = (long long)T * DH * DH;     // per-head K1W/Vq1
    const long long SH  = (long long)T * T * DH;      // per-head A2
    const long long AH  = (long long)T * T * T;       // per-head attn

    // 1) proj = x @ W_kkqvv + b
    launch_gemm(x, 0, 0, D, Wk, 0, 0, 5 * D, proj, 0, 0, 5 * D,
                T, 5 * D, D, 1, 1, 0, bk, nullptr, 0, nullptr, 0, 1);

    // 2) K1W[h] = k1_h @ W_Kq[h]
    launch_gemm(proj + 0, 64, 0, 5 * D, WKq, (long long)DH * DH * DH, 0, DH * DH,
                k1w, HPJ, 0, DH * DH,
                T, DH * DH, DH, 1, H, 0, nullptr, nullptr, 0, nullptr, 0, 1);

    // 3) Vq1[h] = v1_h @ W_Vq[h]
    launch_gemm(proj + 3 * D, 64, 0, 5 * D, WVq, (long long)DH * DH * DH, 0, DH * DH,
                vq1, HPJ, 0, DH * DH,
                T, DH * DH, DH, 1, H, 0, nullptr, nullptr, 0, nullptr, 0, 1);

    // 4+5 fused) logits[h][p][q][t]
    {
        dim3 grid(T / 64, T, H);
        logits_kernel<<<grid, 256>>>(proj, k1w, attn);
    }

    // 6) row stats (max, 1/sum)
    {
        dim3 grid(T, H);
        rowstats_kernel<<<grid, 256>>>(attn, rmax, rinv);
    }

    // 8) A2[h][q][p*64+c] = rowinv[h,q] * sum_t exp(logits/64 - rowmax) * v2_h[t,c]
    //    exp+mask fused into A-load (mode 3)
    launch_gemm(attn, AH, (long long)T * T, T,
                proj + 4 * D, 64, 0, 5 * D,
                A2, SH, DH, T * DH,
                T, DH, T, T, H * T, 0, nullptr, rinv, T, rmax, 3, 1);

    // 9) z[q][h*64+e] = sum_{p,c} A2[h][q][p*64+c] * Vq1[h][(p*64+c)][e]
    cudaMemsetAsync(z, 0, (size_t)T * H * DH * sizeof(float));
    launch_gemm(A2, SH, 0, T * DH,
                vq1, HPJ, 0, DH,
                z, DH, 0, H * DH,
                T, DH, T * DH, 1, H, 0, nullptr, nullptr, 0, nullptr, 0, 16);

    // 10) out = z @ W_out + b_out
    launch_gemm(z, 0, 0, H * DH, Wout, 0, 0, D,
                out, 0, 0, D,
                T, D, H * DH, 1, 1, 0, bout, nullptr, 0, nullptr, 0, 1);
}

// round 3
// speedup vs baseline: 1.5644x; 1.2648x over previous
#include <cuda_runtime.h>
#include <cstdint>

// ---------------------------------------------------------------------------
// Problem constants: B=1, T=256, D=512, H=8, DH=64
// proj layout: [t, 5*512]; chunks k1@0, k2@512, q@1024, v1@1536, v2@2048,
// per head columns h*64..h*64+63 inside each chunk.
// ---------------------------------------------------------------------------
#define T 256
#define D 512
#define H 8
#define DH 64

// Scratch (device globals — allocation-free rule)
__device__ float g_proj[T * 5 * D];
__device__ float g_K1W[H * T * DH * DH];
__device__ float g_Vq1[H * T * DH * DH];
__device__ float g_attn[(long long)H * T * T * T];   // 537MB logits cube
__device__ float g_A2[H * T * T * DH];
__device__ float g_rowmax[H * T];
__device__ float g_rowinv[H * T];
__device__ float g_z[T * H * DH];

// ---------------------------------------------------------------------------
// Generic batched tiled GEMM with full-K=64 smem panels.
//   C[m,n] = sum_k A[m,k] * B(k,n); batch b -> h=b/P, p=b%P
//   transB: B indexed [n*ldb + k]
//   mode 3 (A2 step): A is logits slice [q][t]; on load apply
//     w = (p<=q && t<=q) ? exp(a/64 - rowmax[h,q]) : 0, k_end = min(K, m0+64)
//   ksplit>1: split-K with atomicAdd epilogue
//   rowscale: per-row scale (index h*rsH + m)
// All M,N multiples of 64; all K ranges multiples of 64.
// ---------------------------------------------------------------------------
__global__ __launch_bounds__(256)
void gemm_kernel(const float* __restrict__ A, const float* __restrict__ Bm,
                 float* __restrict__ C,
                 int lda, int ldb, int ldc,
                 int M, int N, int K, int P,
                 long long aH, long long aP,
                 long long bH, long long bP,
                 long long cH, long long cP,
                 int transB,
                 const float* __restrict__ bias,
                 const float* __restrict__ rowscale, int rsH,
                 const float* __restrict__ rowmax,
                 int mode, int ksplit)
{
    int bz = blockIdx.z;
    int b  = bz / ksplit;
    int kc = bz % ksplit;
    int h = b / P, p = b % P;
    A  += (long long)h * aH + (long long)p * aP;
    Bm += (long long)h * bH + (long long)p * bP;
    C  += (long long)h * cH + (long long)p * cP;

    int m0 = blockIdx.y * 64;
    int n0 = blockIdx.x * 64;

    int k_begin = 0, k_end = K;
    if (ksplit > 1) { int kchunk = K / ksplit; k_begin = kc * kchunk; k_end = k_begin + kchunk; }
    if (mode == 3) {
        if (m0 + 63 < p) k_end = k_begin;
        else { int lim = m0 + 64; if (lim < k_end) k_end = lim; }
    }

    __shared__ float As[64][65];   // [k][m]
    __shared__ float Bs[64][65];   // [k][n]

    int tid = threadIdx.x;
    int ty = tid >> 4, tx = tid & 15;

    float acc[4][4] = {};

    for (int k0 = k_begin; k0 < k_end; k0 += 64) {
        if (mode == 3) {
            #pragma unroll 4
            for (int i = tid; i < 4096; i += 256) {
                int r = i >> 6, kk = i & 63;
                int qg = m0 + r, tg = k0 + kk;
                float w = 0.0f;
                if (p <= qg && tg <= qg) {
                    float a = A[(long long)qg * lda + tg];
                    w = __expf(a * 0.015625f - rowmax[h * T + qg]);
                }
                As[kk][r] = w;
            }
        } else {
            #pragma unroll 4
            for (int i = tid; i < 4096; i += 256) {
                int r = i >> 6, kk = i & 63;
                As[kk][r] = A[(long long)(m0 + r) * lda + (k0 + kk)];
            }
        }
        if (transB) {
            #pragma unroll 4
            for (int i = tid; i < 4096; i += 256) {
                int n = i >> 6, kk = i & 63;
                Bs[kk][n] = Bm[(long long)(n0 + n) * ldb + (k0 + kk)];
            }
        } else {
            #pragma unroll 4
            for (int i = tid; i < 4096; i += 256) {
                int kk = i >> 6, n = i & 63;
                Bs[kk][n] = Bm[(long long)(k0 + kk) * ldb + (n0 + n)];
            }
        }
        __syncthreads();

        #pragma unroll 16
        for (int kk = 0; kk < 64; kk++) {
            float a[4], bv[4];
            #pragma unroll
            for (int i = 0; i < 4; i++) a[i] = As[kk][ty * 4 + i];
            #pragma unroll
            for (int j = 0; j < 4; j++) bv[j] = Bs[kk][tx * 4 + j];
            #pragma unroll
            for (int i = 0; i < 4; i++)
                #pragma unroll
                for (int j = 0; j < 4; j++)
                    acc[i][j] += a[i] * bv[j];
        }
        __syncthreads();
    }

    #pragma unroll
    for (int i = 0; i < 4; i++) {
        int m = m0 + ty * 4 + i;
        float scale = rowscale ? rowscale[h * rsH + m] : 1.0f;
        int n = n0 + tx * 4;
        float4 v;
        v.x = acc[i][0] * scale;
        v.y = acc[i][1] * scale;
        v.z = acc[i][2] * scale;
        v.w = acc[i][3] * scale;
        if (bias) { v.x += bias[n]; v.y += bias[n+1]; v.z += bias[n+2]; v.w += bias[n+3]; }
        if (ksplit > 1) {
            atomicAdd(&C[(long long)m * ldc + n + 0], v.x);
            atomicAdd(&C[(long long)m * ldc + n + 1], v.y);
            atomicAdd(&C[(long long)m * ldc + n + 2], v.z);
            atomicAdd(&C[(long long)m * ldc + n + 3], v.w);
        } else {
            *reinterpret_cast<float4*>(&C[(long long)m * ldc + n]) = v;
        }
    }
}

// ---------------------------------------------------------------------------
// Fused steps 4+5: per (h, p, qtile):
//   St[j][q] = sum_i q_h[q,i] * K1W[h][p][j*64+i]   (kept in smem, reuses As)
//   logits[h][p][q][t] = sum_j St[j][q] * k2_h[t,j] for t-tiles tt <= qtile
// grid = (qtile=4, p=256, h=8), block = 256
// ---------------------------------------------------------------------------
__global__ __launch_bounds__(256)
void logits_kernel(const float* __restrict__ proj,
                   const float* __restrict__ k1w,
                   float* __restrict__ attn)
{
    int qt = blockIdx.x;
    int p  = blockIdx.y;
    int h  = blockIdx.z;
    if (qt * 64 + 63 < p) return;

    const float* qmat = proj + 2 * D + h * 64;           // [q][i], ld = 5*D
    const float* k2m  = proj + 1 * D + h * 64;           // [t][j], ld = 5*D
    const float* Bp   = k1w + ((long long)h * T + p) * (DH * DH);  // [j*64+i]
    float* Cb = attn + ((long long)(h * T + p)) * T * T; // [q][t], ld = T

    __shared__ float As[64][65];   // phase1: [i][q]; then reused as St[j][q]
    __shared__ float Bs[64][65];   // phase1: [i][j]; phase2: [j][t]

    int tid = threadIdx.x;
    int ty = tid >> 4, tx = tid & 15;
    int q0 = qt * 64;

    // Phase 1: St = q-tile @ K1W[p]^T  (rows q, cols j, contract i)
    float st[4][4] = {};
    #pragma unroll 4
    for (int i = tid; i < 4096; i += 256) {
        int r = i >> 6, kk = i & 63;
        As[kk][r] = qmat[(long long)(q0 + r) * (5 * D) + kk];
    }
    #pragma unroll 4
    for (int i = tid; i < 4096; i += 256) {
        int j = i >> 6, ii = i & 63;
        Bs[ii][j] = Bp[i];                               // Bp[j*64+ii]
    }
    __syncthreads();

    #pragma unroll 16
    for (int kk = 0; kk < 64; kk++) {
        float a[4], bv[4];
        #pragma unroll
        for (int i = 0; i < 4; i++) a[i] = As[kk][ty * 4 + i];
        #pragma unroll
        for (int j = 0; j < 4; j++) bv[j] = Bs[kk][tx * 4 + j];
        #pragma unroll
        for (int i = 0; i < 4; i++)
            #pragma unroll
            for (int j = 0; j < 4; j++)
                st[i][j] += a[i] * bv[j];
    }
    __syncthreads();                                     // As/Bs reads done

    // store St transposed into As: As[j][q]
    #pragma unroll
    for (int i = 0; i < 4; i++)
        #pragma unroll
        for (int j = 0; j < 4; j++)
            As[tx * 4 + j][ty * 4 + i] = st[i][j];

    // Phase 2: for each t-tile <= qt: L[q][t] = sum_j St[j][q] * k2[t][j]
    for (int tt = 0; tt <= qt; tt++) {
        int t0 = tt * 64;
        #pragma unroll 4
        for (int i = tid; i < 4096; i += 256) {
            int t = i >> 6, jj = i & 63;
            Bs[jj][t] = k2m[(long long)(t0 + t) * (5 * D) + jj];
        }
        __syncthreads();                                 // St + Bs ready

        float acc[4][4] = {};
        #pragma unroll 16
        for (int kk = 0; kk < 64; kk++) {
            float a[4], bv[4];
            #pragma unroll
            for (int i = 0; i < 4; i++) a[i] = As[kk][ty * 4 + i];
            #pragma unroll
            for (int j = 0; j < 4; j++) bv[j] = Bs[kk][tx * 4 + j];
            #pragma unroll
            for (int i = 0; i < 4; i++)
                #pragma unroll
                for (int j = 0; j < 4; j++)
                    acc[i][j] += a[i] * bv[j];
        }
        __syncthreads();                                 // before next Bs overwrite

        #pragma unroll
        for (int i = 0; i < 4; i++) {
            float4 v;
            v.x = acc[i][0]; v.y = acc[i][1]; v.z = acc[i][2]; v.w = acc[i][3];
            *reinterpret_cast<float4*>(&Cb[(long long)(q0 + ty * 4 + i) * T + t0 + tx * 4]) = v;
        }
    }
}

// ---------------------------------------------------------------------------
// Row stats: per (h,q) max and 1/sum of exp(logit/DH - max) over p<=q, t<=q.
// ---------------------------------------------------------------------------
__global__ void rowstats_kernel(const float* __restrict__ attn,
                                float* __restrict__ rowmax,
                                float* __restrict__ rowinv)
{
    int q = blockIdx.x, h = blockIdx.y;
    int tid = threadIdx.x;
    const float inv = 1.0f / (float)DH;

    float m = -1e30f, s = 0.0f;
    for (int p = 0; p <= q; p++) {
        const float* row = attn + (((long long)h * T + p) * T + q) * T;
        for (int t = tid; t <= q; t += 256) {
            float x = row[t] * inv;
            if (x > m) { s *= __expf(m - x); m = x; }
            s += __expf(x - m);
        }
    }

    __shared__ float sm[256], ss[256];
    sm[tid] = m; ss[tid] = s;
    __syncthreads();
    for (int o = 128; o > 0; o >>= 1) {
        if (tid < o) {
            float m2 = sm[tid + o], s2 = ss[tid + o];
            float M = fmaxf(sm[tid], m2);
            ss[tid] = ss[tid] * __expf(sm[tid] - M) + s2 * __expf(m2 - M);
            sm[tid] = M;
        }
        __syncthreads();
    }
    if (tid == 0) {
        rowmax[h * T + q] = sm[0];
        rowinv[h * T + q] = 1.0f / ss[0];
    }
}

// ---------------------------------------------------------------------------
static inline void launch_gemm(const float* A, long long aH, long long aP, int lda,
                               const float* B, long long bH, long long bP, int ldb,
                               float* C, long long cH, long long cP, int ldc,
                               int M, int N, int K, int P, int batch,
                               int transB, const float* bias,
                               const float* rowscale, int rsH,
                               const float* rowmax,
                               int mode, int ksplit)
{
    dim3 grid(N / 64, M / 64, batch * ksplit);
    gemm_kernel<<<grid, 256>>>(A, B, C, lda, ldb, ldc, M, N, K, P,
                               aH, aP, bH, bP, cH, cP,
                               transB, bias, rowscale, rsH, rowmax, mode, ksplit);
}

extern "C" void kernel_launch(void* const* d_in, const int* in_sizes, int n_in,
                              void* d_out, int out_size)
{
    const float* x    = (const float*)d_in[0];   // [256, 512]
    const float* Wk   = (const float*)d_in[1];   // [512, 2560]
    const float* bk   = (const float*)d_in[2];   // [2560]
    const float* WKq  = (const float*)d_in[3];   // [8,64,64,64]
    const float* WVq  = (const float*)d_in[4];   // [8,64,64,64]
    const float* Wout = (const float*)d_in[5];   // [512, 512]
    const float* bout = (const float*)d_in[6];   // [512]
    float* out = (float*)d_out;                  // [256, 512]

    float *proj, *k1w, *vq1, *attn, *A2, *rmax, *rinv, *z;
    cudaGetSymbolAddress((void**)&proj, g_proj);
    cudaGetSymbolAddress((void**)&k1w,  g_K1W);
    cudaGetSymbolAddress((void**)&vq1,  g_Vq1);
    cudaGetSymbolAddress((void**)&attn, g_attn);
    cudaGetSymbolAddress((void**)&A2,   g_A2);
    cudaGetSymbolAddress((void**)&rmax, g_rowmax);
    cudaGetSymbolAddress((void**)&rinv, g_rowinv);
    cudaGetSymbolAddress((void**)&z,    g_z);

    const long long HPJ = (long long)T * DH * DH;     // per-head K1W/Vq1
    const long long SH  = (long long)T * T * DH;      // per-head A2
    const long long AH  = (long long)T * T * T;       // per-head attn

    // 1) proj = x @ W_kkqvv + b
    launch_gemm(x, 0, 0, D, Wk, 0, 0, 5 * D, proj, 0, 0, 5 * D,
                T, 5 * D, D, 1, 1, 0, bk, nullptr, 0, nullptr, 0, 1);

    // 2) K1W[h] = k1_h @ W_Kq[h]
    launch_gemm(proj + 0, 64, 0, 5 * D, WKq, (long long)DH * DH * DH, 0, DH * DH,
                k1w, HPJ, 0, DH * DH,
                T, DH * DH, DH, 1, H, 0, nullptr, nullptr, 0, nullptr, 0, 1);

    // 3) Vq1[h] = v1_h @ W_Vq[h]
    launch_gemm(proj + 3 * D, 64, 0, 5 * D, WVq, (long long)DH * DH * DH, 0, DH * DH,
                vq1, HPJ, 0, DH * DH,
                T, DH * DH, DH, 1, H, 0, nullptr, nullptr, 0, nullptr, 0, 1);

    // 4+5 fused) logits[h][p][q][t]
    {
        dim3 grid(T / 64, T, H);
        logits_kernel<<<grid, 256>>>(proj, k1w, attn);
    }

    // 6) row stats (max, 1/sum)
    {
        dim3 grid(T, H);
        rowstats_kernel<<<grid, 256>>>(attn, rmax, rinv);
    }

    // 8) A2[h][q][p*64+c] = rowinv[h,q] * sum_t exp(logits/64 - rowmax) * v2_h[t,c]
    launch_gemm(attn, AH, (long long)T * T, T,
                proj + 4 * D, 64, 0, 5 * D,
                A2, SH, DH, T * DH,
                T, DH, T, T, H * T, 0, nullptr, rinv, T, rmax, 3, 1);

    // 9) z[q][h*64+e] = sum_{p,c} A2[h][q][p*64+c] * Vq1[h][(p*64+c)][e]
    cudaMemsetAsync(z, 0, (size_t)T * H * DH * sizeof(float));
    launch_gemm(A2, SH, 0, T * DH,
                vq1, HPJ, 0, DH,
                z, DH, 0, H * DH,
                T, DH, T * DH, 1, H, 0, nullptr, nullptr, 0, nullptr, 0, 16);

    // 10) out = z @ W_out + b_out
    launch_gemm(z, 0, 0, H * DH, Wout, 0, 0, D,
                out, 0, 0, D,
                T, D, H * DH, 1, 1, 0, bout, nullptr, 0, nullptr, 0, 1);
}

// round 4
// speedup vs baseline: 1.6680x; 1.0662x over previous
#include <cuda_runtime.h>
#include <cstdint>

// ---------------------------------------------------------------------------
// Problem constants: B=1, T=256, D=512, H=8, DH=64
// proj layout: [t, 5*512]; chunks k1@0, k2@512, q@1024, v1@1536, v2@2048.
// ---------------------------------------------------------------------------
#define T 256
#define D 512
#define H 8
#define DH 64

// Packed fp32x2 FMA (sm_100+): d.lo=a.lo*b.lo+c.lo, d.hi likewise.
#define FMA2(acc, a, b) asm("fma.rn.f32x2 %0, %1, %2, %0;" : "+l"(acc) : "l"(a), "l"(b))
#define DUP2(dst, f)    asm("mov.b64 %0, {%1, %1};" : "=l"(dst) : "r"(__float_as_uint(f)))
static __device__ __forceinline__ float lo2(unsigned long long v) { return __uint_as_float((unsigned int)v); }
static __device__ __forceinline__ float hi2(unsigned long long v) { return __uint_as_float((unsigned int)(v >> 32)); }

// Scratch (device globals — allocation-free rule)
__device__ float g_proj[T * 5 * D];
__device__ float g_K1W[H * T * DH * DH];
__device__ float g_Vq1[H * T * DH * DH];
__device__ float g_attn[(long long)H * T * T * T];   // logits cube
__device__ float g_A2[H * T * T * DH];
__device__ float g_rowmax[H * T];
__device__ float g_rowinv[H * T];
__device__ float g_z[T * H * DH];

// ---------------------------------------------------------------------------
// Generic batched tiled GEMM, 64x64 tile, 128 threads, 8x4 per thread, FFMA2.
//   C[m,n] = sum_k A[m,k] * B(k,n); batch b -> h=b/P, p=b%P
//   transB: B indexed [n*ldb + k]
//   mode 3 (A2): A is logits slice [q][t]; on load apply
//     w = (p<=q && t<=q) ? exp(a/64 - rowmax[h,q]) : 0, k_end = min(K, m0+64)
//   ksplit>1: split-K with atomicAdd epilogue; rowscale: per-row scale.
// All M,N multiples of 64; all K ranges multiples of 64.
// ---------------------------------------------------------------------------
__global__ __launch_bounds__(128)
void gemm_kernel(const float* __restrict__ A, const float* __restrict__ Bm,
                 float* __restrict__ C,
                 int lda, int ldb, int ldc,
                 int M, int N, int K, int P,
                 long long aH, long long aP,
                 long long bH, long long bP,
                 long long cH, long long cP,
                 int transB,
                 const float* __restrict__ bias,
                 const float* __restrict__ rowscale, int rsH,
                 const float* __restrict__ rowmax,
                 int mode, int ksplit)
{
    int bz = blockIdx.z;
    int b  = bz / ksplit;
    int kc = bz % ksplit;
    int h = b / P, p = b % P;
    A  += (long long)h * aH + (long long)p * aP;
    Bm += (long long)h * bH + (long long)p * bP;
    C  += (long long)h * cH + (long long)p * cP;

    int m0 = blockIdx.y * 64;
    int n0 = blockIdx.x * 64;

    int k_begin = 0, k_end = K;
    if (ksplit > 1) { int kchunk = K / ksplit; k_begin = kc * kchunk; k_end = k_begin + kchunk; }
    if (mode == 3) {
        if (m0 + 63 < p) k_end = k_begin;
        else { int lim = m0 + 64; if (lim < k_end) k_end = lim; }
    }

    __shared__ float As[64][66];   // [k][m], stride 66 keeps 8B alignment
    __shared__ float Bs[64][66];   // [k][n]

    int tid = threadIdx.x;
    int ty = tid >> 4, tx = tid & 15;   // ty: 8 row-group, tx: 16 col-group

    unsigned long long acc2[4][4];      // [rowpair][col]
    #pragma unroll
    for (int i = 0; i < 4; i++)
        #pragma unroll
        for (int j = 0; j < 4; j++) acc2[i][j] = 0ULL;

    for (int k0 = k_begin; k0 < k_end; k0 += 64) {
        if (mode == 3) {
            #pragma unroll 8
            for (int i = tid; i < 4096; i += 128) {
                int r = i >> 6, kk = i & 63;
                int qg = m0 + r, tg = k0 + kk;
                float w = 0.0f;
                if (p <= qg && tg <= qg) {
                    float a = A[(long long)qg * lda + tg];
                    w = __expf(a * 0.015625f - rowmax[h * T + qg]);
                }
                As[kk][r] = w;
            }
        } else {
            #pragma unroll 8
            for (int i = tid; i < 4096; i += 128) {
                int r = i >> 6, kk = i & 63;
                As[kk][r] = A[(long long)(m0 + r) * lda + (k0 + kk)];
            }
        }
        if (transB) {
            #pragma unroll 8
            for (int i = tid; i < 4096; i += 128) {
                int n = i >> 6, kk = i & 63;
                Bs[kk][n] = Bm[(long long)(n0 + n) * ldb + (k0 + kk)];
            }
        } else {
            #pragma unroll 8
            for (int i = tid; i < 4096; i += 128) {
                int kk = i >> 6, n = i & 63;
                Bs[kk][n] = Bm[(long long)(k0 + kk) * ldb + (n0 + n)];
            }
        }
        __syncthreads();

        #pragma unroll 16
        for (int kk = 0; kk < 64; kk++) {
            const unsigned long long* arow =
                reinterpret_cast<const unsigned long long*>(&As[kk][ty * 8]);
            unsigned long long a0 = arow[0], a1 = arow[1], a2v = arow[2], a3 = arow[3];
            float bf0 = Bs[kk][tx * 4 + 0];
            float bf1 = Bs[kk][tx * 4 + 1];
            float bf2 = Bs[kk][tx * 4 + 2];
            float bf3 = Bs[kk][tx * 4 + 3];
            unsigned long long b0, b1, b2, b3;
            DUP2(b0, bf0); DUP2(b1, bf1); DUP2(b2, bf2); DUP2(b3, bf3);
            FMA2(acc2[0][0], a0, b0); FMA2(acc2[0][1], a0, b1);
            FMA2(acc2[0][2], a0, b2); FMA2(acc2[0][3], a0, b3);
            FMA2(acc2[1][0], a1, b0); FMA2(acc2[1][1], a1, b1);
            FMA2(acc2[1][2], a1, b2); FMA2(acc2[1][3], a1, b3);
            FMA2(acc2[2][0], a2v, b0); FMA2(acc2[2][1], a2v, b1);
            FMA2(acc2[2][2], a2v, b2); FMA2(acc2[2][3], a2v, b3);
            FMA2(acc2[3][0], a3, b0); FMA2(acc2[3][1], a3, b1);
            FMA2(acc2[3][2], a3, b2); FMA2(acc2[3][3], a3, b3);
        }
        __syncthreads();
    }

    int n = n0 + tx * 4;
    float4 bv4 = {0,0,0,0};
    if (bias) { bv4.x = bias[n]; bv4.y = bias[n+1]; bv4.z = bias[n+2]; bv4.w = bias[n+3]; }
    #pragma unroll
    for (int ip = 0; ip < 4; ip++) {
        #pragma unroll
        for (int half = 0; half < 2; half++) {
            int m = m0 + ty * 8 + ip * 2 + half;
            float scale = rowscale ? rowscale[h * rsH + m] : 1.0f;
            float4 v;
            v.x = (half ? hi2(acc2[ip][0]) : lo2(acc2[ip][0])) * scale + bv4.x;
            v.y = (half ? hi2(acc2[ip][1]) : lo2(acc2[ip][1])) * scale + bv4.y;
            v.z = (half ? hi2(acc2[ip][2]) : lo2(acc2[ip][2])) * scale + bv4.z;
            v.w = (half ? hi2(acc2[ip][3]) : lo2(acc2[ip][3])) * scale + bv4.w;
            if (ksplit > 1) {
                atomicAdd(&C[(long long)m * ldc + n + 0], v.x);
                atomicAdd(&C[(long long)m * ldc + n + 1], v.y);
                atomicAdd(&C[(long long)m * ldc + n + 2], v.z);
                atomicAdd(&C[(long long)m * ldc + n + 3], v.w);
            } else {
                *reinterpret_cast<float4*>(&C[(long long)m * ldc + n]) = v;
            }
        }
    }
}

// ---------------------------------------------------------------------------
// Fused steps 4+5: per (h, p, qtile):
//   St[j][q] = sum_i q_h[q,i] * K1W[h][p][j*64+i]   (kept in smem, reuses As)
//   logits[h][p][q][t] = sum_j St[j][q] * k2_h[t,j] for t-tiles tt <= qtile
// grid = (qtile=4, p=256, h=8), block = 128
// ---------------------------------------------------------------------------
__global__ __launch_bounds__(128)
void logits_kernel(const float* __restrict__ proj,
                   const float* __restrict__ k1w,
                   float* __restrict__ attn)
{
    int qt = blockIdx.x;
    int p  = blockIdx.y;
    int h  = blockIdx.z;
    if (qt * 64 + 63 < p) return;

    const float* qmat = proj + 2 * D + h * 64;           // [q][i], ld = 5*D
    const float* k2m  = proj + 1 * D + h * 64;           // [t][j], ld = 5*D
    const float* Bp   = k1w + ((long long)h * T + p) * (DH * DH);  // [j*64+i]
    float* Cb = attn + ((long long)(h * T + p)) * T * T; // [q][t], ld = T

    __shared__ float As[64][66];   // phase1 [i][q]; then St[j][q]
    __shared__ float Bs[64][66];   // phase1 [i][j]; phase2 [j][t]

    int tid = threadIdx.x;
    int ty = tid >> 4, tx = tid & 15;
    int q0 = qt * 64;

    // Phase 1: St[q][j] = sum_i q[q,i] * K1W[j*64+i]
    unsigned long long st2[4][4];
    #pragma unroll
    for (int i = 0; i < 4; i++)
        #pragma unroll
        for (int j = 0; j < 4; j++) st2[i][j] = 0ULL;

    #pragma unroll 8
    for (int i = tid; i < 4096; i += 128) {
        int r = i >> 6, kk = i & 63;
        As[kk][r] = qmat[(long long)(q0 + r) * (5 * D) + kk];
    }
    #pragma unroll 8
    for (int i = tid; i < 4096; i += 128) {
        int j = i >> 6, ii = i & 63;
        Bs[ii][j] = Bp[i];                               // Bp[j*64+ii]
    }
    __syncthreads();

    #pragma unroll 16
    for (int kk = 0; kk < 64; kk++) {
        const unsigned long long* arow =
            reinterpret_cast<const unsigned long long*>(&As[kk][ty * 8]);
        unsigned long long a0 = arow[0], a1 = arow[1], a2v = arow[2], a3 = arow[3];
        float bf0 = Bs[kk][tx * 4 + 0];
        float bf1 = Bs[kk][tx * 4 + 1];
        float bf2 = Bs[kk][tx * 4 + 2];
        float bf3 = Bs[kk][tx * 4 + 3];
        unsigned long long b0, b1, b2, b3;
        DUP2(b0, bf0); DUP2(b1, bf1); DUP2(b2, bf2); DUP2(b3, bf3);
        FMA2(st2[0][0], a0, b0); FMA2(st2[0][1], a0, b1);
        FMA2(st2[0][2], a0, b2); FMA2(st2[0][3], a0, b3);
        FMA2(st2[1][0], a1, b0); FMA2(st2[1][1], a1, b1);
        FMA2(st2[1][2], a1, b2); FMA2(st2[1][3], a1, b3);
        FMA2(st2[2][0], a2v, b0); FMA2(st2[2][1], a2v, b1);
        FMA2(st2[2][2], a2v, b2); FMA2(st2[2][3], a2v, b3);
        FMA2(st2[3][0], a3, b0); FMA2(st2[3][1], a3, b1);
        FMA2(st2[3][2], a3, b2); FMA2(st2[3][3], a3, b3);
    }
    __syncthreads();                                     // As/Bs reads done

    // store St transposed into As: As[j][q]
    #pragma unroll
    for (int ip = 0; ip < 4; ip++)
        #pragma unroll
        for (int j = 0; j < 4; j++) {
            As[tx * 4 + j][ty * 8 + ip * 2 + 0] = lo2(st2[ip][j]);
            As[tx * 4 + j][ty * 8 + ip * 2 + 1] = hi2(st2[ip][j]);
        }

    // Phase 2: per t-tile <= qt: L[q][t] = sum_j St[j][q] * k2[t][j]
    for (int tt = 0; tt <= qt; tt++) {
        int t0 = tt * 64;
        #pragma unroll 8
        for (int i = tid; i < 4096; i += 128) {
            int t = i >> 6, jj = i & 63;
            Bs[jj][t] = k2m[(long long)(t0 + t) * (5 * D) + jj];
        }
        __syncthreads();                                 // St + Bs ready

        unsigned long long acc2[4][4];
        #pragma unroll
        for (int i = 0; i < 4; i++)
            #pragma unroll
            for (int j = 0; j < 4; j++) acc2[i][j] = 0ULL;

        #pragma unroll 16
        for (int kk = 0; kk < 64; kk++) {
            const unsigned long long* arow =
                reinterpret_cast<const unsigned long long*>(&As[kk][ty * 8]);
            unsigned long long a0 = arow[0], a1 = arow[1], a2v = arow[2], a3 = arow[3];
            float bf0 = Bs[kk][tx * 4 + 0];
            float bf1 = Bs[kk][tx * 4 + 1];
            float bf2 = Bs[kk][tx * 4 + 2];
            float bf3 = Bs[kk][tx * 4 + 3];
            unsigned long long b0, b1, b2, b3;
            DUP2(b0, bf0); DUP2(b1, bf1); DUP2(b2, bf2); DUP2(b3, bf3);
            FMA2(acc2[0][0], a0, b0); FMA2(acc2[0][1], a0, b1);
            FMA2(acc2[0][2], a0, b2); FMA2(acc2[0][3], a0, b3);
            FMA2(acc2[1][0], a1, b0); FMA2(acc2[1][1], a1, b1);
            FMA2(acc2[1][2], a1, b2); FMA2(acc2[1][3], a1, b3);
            FMA2(acc2[2][0], a2v, b0); FMA2(acc2[2][1], a2v, b1);
            FMA2(acc2[2][2], a2v, b2); FMA2(acc2[2][3], a2v, b3);
            FMA2(acc2[3][0], a3, b0); FMA2(acc2[3][1], a3, b1);
            FMA2(acc2[3][2], a3, b2); FMA2(acc2[3][3], a3, b3);
        }
        __syncthreads();                                 // before next Bs fill

        #pragma unroll
        for (int ip = 0; ip < 4; ip++) {
            #pragma unroll
            for (int half = 0; half < 2; half++) {
                int q = q0 + ty * 8 + ip * 2 + half;
                float4 v;
                v.x = half ? hi2(acc2[ip][0]) : lo2(acc2[ip][0]);
                v.y = half ? hi2(acc2[ip][1]) : lo2(acc2[ip][1]);
                v.z = half ? hi2(acc2[ip][2]) : lo2(acc2[ip][2]);
                v.w = half ? hi2(acc2[ip][3]) : lo2(acc2[ip][3]);
                *reinterpret_cast<float4*>(&Cb[(long long)q * T + t0 + tx * 4]) = v;
            }
        }
    }
}

// ---------------------------------------------------------------------------
// Row stats: per (h,q) max and 1/sum of exp(logit/DH - max) over p<=q, t<=q.
// ---------------------------------------------------------------------------
__global__ void rowstats_kernel(const float* __restrict__ attn,
                                float* __restrict__ rowmax,
                                float* __restrict__ rowinv)
{
    int q = blockIdx.x, h = blockIdx.y;
    int tid = threadIdx.x;
    const float inv = 1.0f / (float)DH;

    float m = -1e30f, s = 0.0f;
    for (int p = 0; p <= q; p++) {
        const float* row = attn + (((long long)h * T + p) * T + q) * T;
        for (int t = tid; t <= q; t += 256) {
            float x = row[t] * inv;
            if (x > m) { s *= __expf(m - x); m = x; }
            s += __expf(x - m);
        }
    }

    __shared__ float sm[256], ss[256];
    sm[tid] = m; ss[tid] = s;
    __syncthreads();
    for (int o = 128; o > 0; o >>= 1) {
        if (tid < o) {
            float m2 = sm[tid + o], s2 = ss[tid + o];
            float M = fmaxf(sm[tid], m2);
            ss[tid] = ss[tid] * __expf(sm[tid] - M) + s2 * __expf(m2 - M);
            sm[tid] = M;
        }
        __syncthreads();
    }
    if (tid == 0) {
        rowmax[h * T + q] = sm[0];
        rowinv[h * T + q] = 1.0f / ss[0];
    }
}

// ---------------------------------------------------------------------------
static inline void launch_gemm(const float* A, long long aH, long long aP, int lda,
                               const float* B, long long bH, long long bP, int ldb,
                               float* C, long long cH, long long cP, int ldc,
                               int M, int N, int K, int P, int batch,
                               int transB, const float* bias,
                               const float* rowscale, int rsH,
                               const float* rowmax,
                               int mode, int ksplit)
{
    dim3 grid(N / 64, M / 64, batch * ksplit);
    gemm_kernel<<<grid, 128>>>(A, B, C, lda, ldb, ldc, M, N, K, P,
                               aH, aP, bH, bP, cH, cP,
                               transB, bias, rowscale, rsH, rowmax, mode, ksplit);
}

extern "C" void kernel_launch(void* const* d_in, const int* in_sizes, int n_in,
                              void* d_out, int out_size)
{
    const float* x    = (const float*)d_in[0];   // [256, 512]
    const float* Wk   = (const float*)d_in[1];   // [512, 2560]
    const float* bk   = (const float*)d_in[2];   // [2560]
    const float* WKq  = (const float*)d_in[3];   // [8,64,64,64]
    const float* WVq  = (const float*)d_in[4];   // [8,64,64,64]
    const float* Wout = (const float*)d_in[5];   // [512, 512]
    const float* bout = (const float*)d_in[6];   // [512]
    float* out = (float*)d_out;                  // [256, 512]

    float *proj, *k1w, *vq1, *attn, *A2, *rmax, *rinv, *z;
    cudaGetSymbolAddress((void**)&proj, g_proj);
    cudaGetSymbolAddress((void**)&k1w,  g_K1W);
    cudaGetSymbolAddress((void**)&vq1,  g_Vq1);
    cudaGetSymbolAddress((void**)&attn, g_attn);
    cudaGetSymbolAddress((void**)&A2,   g_A2);
    cudaGetSymbolAddress((void**)&rmax, g_rowmax);
    cudaGetSymbolAddress((void**)&rinv, g_rowinv);
    cudaGetSymbolAddress((void**)&z,    g_z);

    const long long HPJ = (long long)T * DH * DH;     // per-head K1W/Vq1
    const long long SH  = (long long)T * T * DH;      // per-head A2
    const long long AH  = (long long)T * T * T;       // per-head attn

    // 1) proj = x @ W_kkqvv + b
    launch_gemm(x, 0, 0, D, Wk, 0, 0, 5 * D, proj, 0, 0, 5 * D,
                T, 5 * D, D, 1, 1, 0, bk, nullptr, 0, nullptr, 0, 1);

    // 2) K1W[h] = k1_h @ W_Kq[h]
    launch_gemm(proj + 0, 64, 0, 5 * D, WKq, (long long)DH * DH * DH, 0, DH * DH,
                k1w, HPJ, 0, DH * DH,
                T, DH * DH, DH, 1, H, 0, nullptr, nullptr, 0, nullptr, 0, 1);

    // 3) Vq1[h] = v1_h @ W_Vq[h]
    launch_gemm(proj + 3 * D, 64, 0, 5 * D, WVq, (long long)DH * DH * DH, 0, DH * DH,
                vq1, HPJ, 0, DH * DH,
                T, DH * DH, DH, 1, H, 0, nullptr, nullptr, 0, nullptr, 0, 1);

    // 4+5 fused) logits[h][p][q][t]
    {
        dim3 grid(T / 64, T, H);
        logits_kernel<<<grid, 128>>>(proj, k1w, attn);
    }

    // 6) row stats (max, 1/sum)
    {
        dim3 grid(T, H);
        rowstats_kernel<<<grid, 256>>>(attn, rmax, rinv);
    }

    // 8) A2[h][q][p*64+c] = rowinv[h,q] * sum_t exp(logits/64 - rowmax) * v2_h[t,c]
    launch_gemm(attn, AH, (long long)T * T, T,
                proj + 4 * D, 64, 0, 5 * D,
                A2, SH, DH, T * DH,
                T, DH, T, T, H * T, 0, nullptr, rinv, T, rmax, 3, 1);

    // 9) z[q][h*64+e] = sum_{p,c} A2[h][q][p*64+c] * Vq1[h][(p*64+c)][e]
    cudaMemsetAsync(z, 0, (size_t)T * H * DH * sizeof(float));
    launch_gemm(A2, SH, 0, T * DH,
                vq1, HPJ, 0, DH,
                z, DH, 0, H * DH,
                T, DH, T * DH, 1, H, 0, nullptr, nullptr, 0, nullptr, 0, 16);

    // 10) out = z @ W_out + b_out
    launch_gemm(z, 0, 0, H * DH, Wout, 0, 0, D,
                out, 0, 0, D,
                T, D, H * DH, 1, 1, 0, bout, nullptr, 0, nullptr, 0, 1);
}

// round 5
// speedup vs baseline: 2.2922x; 1.3742x over previous
#include <cuda_runtime.h>
#include <cstdint>

// ---------------------------------------------------------------------------
// Problem constants: B=1, T=256, D=512, H=8, DH=64
// proj layout: [t, 5*512]; chunks k1@0, k2@512, q@1024, v1@1536, v2@2048.
// ---------------------------------------------------------------------------
#define T 256
#define D 512
#define H 8
#define DH 64

// Packed fp32x2 FMA (sm_100+)
#define FMA2(acc, a, b) asm("fma.rn.f32x2 %0, %1, %2, %0;" : "+l"(acc) : "l"(a), "l"(b))
#define DUP2(dst, f)    asm("mov.b64 %0, {%1, %1};" : "=l"(dst) : "r"(__float_as_uint(f)))
static __device__ __forceinline__ float lo2(unsigned long long v) { return __uint_as_float((unsigned int)v); }
static __device__ __forceinline__ float hi2(unsigned long long v) { return __uint_as_float((unsigned int)(v >> 32)); }

// Scratch (device globals — allocation-free rule)
__device__ float g_proj[T * 5 * D];
__device__ float g_K1W[H * T * DH * DH];
__device__ float g_Vq1[H * T * DH * DH];
__device__ float g_attn[(long long)H * T * T * T];   // exp'd, pre-masked weights
__device__ float g_A2[H * T * T * DH];
__device__ float g_spart[H * T * T];                 // [h][p][q] partial row sums
__device__ float g_rowinv[H * T];
__device__ float g_z[T * H * DH];

// ---------------------------------------------------------------------------
// Generic batched tiled GEMM, 64x64 tile, 128 threads, 8x4/thread, FFMA2.
//   C[m,n] = sum_k A[m,k] * B(k,n); batch b -> h=b/P, p=b%P
//   transB: B indexed [n*ldb + k]
//   mode 2 (A2): k_end = min(K, m0+64); if m0+63 < p -> zero output tile.
//                (A values are pre-masked exp weights; plain loads.)
//   ksplit>1: split-K with atomicAdd epilogue; rowscale: per-row scale.
// All M,N multiples of 64; all K ranges multiples of 64.
// ---------------------------------------------------------------------------
__global__ __launch_bounds__(128)
void gemm_kernel(const float* __restrict__ A, const float* __restrict__ Bm,
                 float* __restrict__ C,
                 int lda, int ldb, int ldc,
                 int M, int N, int K, int P,
                 long long aH, long long aP,
                 long long bH, long long bP,
                 long long cH, long long cP,
                 int transB,
                 const float* __restrict__ bias,
                 const float* __restrict__ rowscale, int rsH,
                 int mode, int ksplit)
{
    int bz = blockIdx.z;
    int b  = bz / ksplit;
    int kc = bz % ksplit;
    int h = b / P, p = b % P;
    A  += (long long)h * aH + (long long)p * aP;
    Bm += (long long)h * bH + (long long)p * bP;
    C  += (long long)h * cH + (long long)p * cP;

    int m0 = blockIdx.y * 64;
    int n0 = blockIdx.x * 64;

    int k_begin = 0, k_end = K;
    if (ksplit > 1) { int kchunk = K / ksplit; k_begin = kc * kchunk; k_end = k_begin + kchunk; }
    if (mode == 2) {
        if (m0 + 63 < p) k_end = k_begin;                 // all-zero tile
        else { int lim = m0 + 64; if (lim < k_end) k_end = lim; }
    }

    __shared__ float As[64][66];   // [k][m]
    __shared__ float Bs[64][66];   // [k][n]

    int tid = threadIdx.x;
    int ty = tid >> 4, tx = tid & 15;

    unsigned long long acc2[4][4];
    #pragma unroll
    for (int i = 0; i < 4; i++)
        #pragma unroll
        for (int j = 0; j < 4; j++) acc2[i][j] = 0ULL;

    for (int k0 = k_begin; k0 < k_end; k0 += 64) {
        #pragma unroll 8
        for (int i = tid; i < 4096; i += 128) {
            int r = i >> 6, kk = i & 63;
            As[kk][r] = A[(long long)(m0 + r) * lda + (k0 + kk)];
        }
        if (transB) {
            #pragma unroll 8
            for (int i = tid; i < 4096; i += 128) {
                int n = i >> 6, kk = i & 63;
                Bs[kk][n] = Bm[(long long)(n0 + n) * ldb + (k0 + kk)];
            }
        } else {
            #pragma unroll 8
            for (int i = tid; i < 4096; i += 128) {
                int kk = i >> 6, n = i & 63;
                Bs[kk][n] = Bm[(long long)(k0 + kk) * ldb + (n0 + n)];
            }
        }
        __syncthreads();

        #pragma unroll 16
        for (int kk = 0; kk < 64; kk++) {
            const unsigned long long* arow =
                reinterpret_cast<const unsigned long long*>(&As[kk][ty * 8]);
            unsigned long long a0 = arow[0], a1 = arow[1], a2v = arow[2], a3 = arow[3];
            float bf0 = Bs[kk][tx * 4 + 0];
            float bf1 = Bs[kk][tx * 4 + 1];
            float bf2 = Bs[kk][tx * 4 + 2];
            float bf3 = Bs[kk][tx * 4 + 3];
            unsigned long long b0, b1, b2, b3;
            DUP2(b0, bf0); DUP2(b1, bf1); DUP2(b2, bf2); DUP2(b3, bf3);
            FMA2(acc2[0][0], a0, b0); FMA2(acc2[0][1], a0, b1);
            FMA2(acc2[0][2], a0, b2); FMA2(acc2[0][3], a0, b3);
            FMA2(acc2[1][0], a1, b0); FMA2(acc2[1][1], a1, b1);
            FMA2(acc2[1][2], a1, b2); FMA2(acc2[1][3], a1, b3);
            FMA2(acc2[2][0], a2v, b0); FMA2(acc2[2][1], a2v, b1);
            FMA2(acc2[2][2], a2v, b2); FMA2(acc2[2][3], a2v, b3);
            FMA2(acc2[3][0], a3, b0); FMA2(acc2[3][1], a3, b1);
            FMA2(acc2[3][2], a3, b2); FMA2(acc2[3][3], a3, b3);
        }
        __syncthreads();
    }

    int n = n0 + tx * 4;
    float4 bv4 = {0,0,0,0};
    if (bias) { bv4.x = bias[n]; bv4.y = bias[n+1]; bv4.z = bias[n+2]; bv4.w = bias[n+3]; }
    #pragma unroll
    for (int ip = 0; ip < 4; ip++) {
        #pragma unroll
        for (int half = 0; half < 2; half++) {
            int m = m0 + ty * 8 + ip * 2 + half;
            float scale = rowscale ? rowscale[h * rsH + m] : 1.0f;
            float4 v;
            v.x = (half ? hi2(acc2[ip][0]) : lo2(acc2[ip][0])) * scale + bv4.x;
            v.y = (half ? hi2(acc2[ip][1]) : lo2(acc2[ip][1])) * scale + bv4.y;
            v.z = (half ? hi2(acc2[ip][2]) : lo2(acc2[ip][2])) * scale + bv4.z;
            v.w = (half ? hi2(acc2[ip][3]) : lo2(acc2[ip][3])) * scale + bv4.w;
            if (ksplit > 1) {
                atomicAdd(&C[(long long)m * ldc + n + 0], v.x);
                atomicAdd(&C[(long long)m * ldc + n + 1], v.y);
                atomicAdd(&C[(long long)m * ldc + n + 2], v.z);
                atomicAdd(&C[(long long)m * ldc + n + 3], v.w);
            } else {
                *reinterpret_cast<float4*>(&C[(long long)m * ldc + n]) = v;
            }
        }
    }
}

// ---------------------------------------------------------------------------
// Fused steps 4+5+exp+partial-softmax: per (h, p, qtile):
//   St[j][q] = sum_i q_h[q,i] * K1W[h][p][j*64+i]
//   e[q][t]  = (q>=p && t<=q) ? exp(logit/64) : 0   for t-tiles tt <= qtile
//   attn[h][p][q][t] = e;   s_part[h][p][q] = sum_t e
// grid = (qtile=4, p=256, h=8), block = 128
// ---------------------------------------------------------------------------
__global__ __launch_bounds__(128)
void logits_kernel(const float* __restrict__ proj,
                   const float* __restrict__ k1w,
                   float* __restrict__ attn,
                   float* __restrict__ s_part)
{
    int qt = blockIdx.x;
    int p  = blockIdx.y;
    int h  = blockIdx.z;
    if (qt * 64 + 63 < p) return;

    const float* qmat = proj + 2 * D + h * 64;           // [q][i], ld = 5*D
    const float* k2m  = proj + 1 * D + h * 64;           // [t][j], ld = 5*D
    const float* Bp   = k1w + ((long long)h * T + p) * (DH * DH);  // [j*64+i]
    float* Cb = attn + ((long long)(h * T + p)) * T * T; // [q][t], ld = T

    __shared__ float As[64][66];   // phase1 [i][q]; then St[j][q]
    __shared__ float Bs[64][66];   // phase1 [i][j]; phase2 [j][t]

    int tid = threadIdx.x;
    int ty = tid >> 4, tx = tid & 15;
    int q0 = qt * 64;

    // Phase 1: St[q][j] = sum_i q[q,i] * K1W[j*64+i]
    unsigned long long st2[4][4];
    #pragma unroll
    for (int i = 0; i < 4; i++)
        #pragma unroll
        for (int j = 0; j < 4; j++) st2[i][j] = 0ULL;

    #pragma unroll 8
    for (int i = tid; i < 4096; i += 128) {
        int r = i >> 6, kk = i & 63;
        As[kk][r] = qmat[(long long)(q0 + r) * (5 * D) + kk];
    }
    #pragma unroll 8
    for (int i = tid; i < 4096; i += 128) {
        int j = i >> 6, ii = i & 63;
        Bs[ii][j] = Bp[i];
    }
    __syncthreads();

    #pragma unroll 16
    for (int kk = 0; kk < 64; kk++) {
        const unsigned long long* arow =
            reinterpret_cast<const unsigned long long*>(&As[kk][ty * 8]);
        unsigned long long a0 = arow[0], a1 = arow[1], a2v = arow[2], a3 = arow[3];
        float bf0 = Bs[kk][tx * 4 + 0];
        float bf1 = Bs[kk][tx * 4 + 1];
        float bf2 = Bs[kk][tx * 4 + 2];
        float bf3 = Bs[kk][tx * 4 + 3];
        unsigned long long b0, b1, b2, b3;
        DUP2(b0, bf0); DUP2(b1, bf1); DUP2(b2, bf2); DUP2(b3, bf3);
        FMA2(st2[0][0], a0, b0); FMA2(st2[0][1], a0, b1);
        FMA2(st2[0][2], a0, b2); FMA2(st2[0][3], a0, b3);
        FMA2(st2[1][0], a1, b0); FMA2(st2[1][1], a1, b1);
        FMA2(st2[1][2], a1, b2); FMA2(st2[1][3], a1, b3);
        FMA2(st2[2][0], a2v, b0); FMA2(st2[2][1], a2v, b1);
        FMA2(st2[2][2], a2v, b2); FMA2(st2[2][3], a2v, b3);
        FMA2(st2[3][0], a3, b0); FMA2(st2[3][1], a3, b1);
        FMA2(st2[3][2], a3, b2); FMA2(st2[3][3], a3, b3);
    }
    __syncthreads();

    // store St transposed into As: As[j][q]
    #pragma unroll
    for (int ip = 0; ip < 4; ip++)
        #pragma unroll
        for (int j = 0; j < 4; j++) {
            As[tx * 4 + j][ty * 8 + ip * 2 + 0] = lo2(st2[ip][j]);
            As[tx * 4 + j][ty * 8 + ip * 2 + 1] = hi2(st2[ip][j]);
        }

    float srow[8];
    #pragma unroll
    for (int r = 0; r < 8; r++) srow[r] = 0.0f;

    // Phase 2: per t-tile <= qt: exp'd, masked weights + per-row sums
    for (int tt = 0; tt <= qt; tt++) {
        int t0 = tt * 64;
        #pragma unroll 8
        for (int i = tid; i < 4096; i += 128) {
            int t = i >> 6, jj = i & 63;
            Bs[jj][t] = k2m[(long long)(t0 + t) * (5 * D) + jj];
        }
        __syncthreads();

        unsigned long long acc2[4][4];
        #pragma unroll
        for (int i = 0; i < 4; i++)
            #pragma unroll
            for (int j = 0; j < 4; j++) acc2[i][j] = 0ULL;

        #pragma unroll 16
        for (int kk = 0; kk < 64; kk++) {
            const unsigned long long* arow =
                reinterpret_cast<const unsigned long long*>(&As[kk][ty * 8]);
            unsigned long long a0 = arow[0], a1 = arow[1], a2v = arow[2], a3 = arow[3];
            float bf0 = Bs[kk][tx * 4 + 0];
            float bf1 = Bs[kk][tx * 4 + 1];
            float bf2 = Bs[kk][tx * 4 + 2];
            float bf3 = Bs[kk][tx * 4 + 3];
            unsigned long long b0, b1, b2, b3;
            DUP2(b0, bf0); DUP2(b1, bf1); DUP2(b2, bf2); DUP2(b3, bf3);
            FMA2(acc2[0][0], a0, b0); FMA2(acc2[0][1], a0, b1);
            FMA2(acc2[0][2], a0, b2); FMA2(acc2[0][3], a0, b3);
            FMA2(acc2[1][0], a1, b0); FMA2(acc2[1][1], a1, b1);
            FMA2(acc2[1][2], a1, b2); FMA2(acc2[1][3], a1, b3);
            FMA2(acc2[2][0], a2v, b0); FMA2(acc2[2][1], a2v, b1);
            FMA2(acc2[2][2], a2v, b2); FMA2(acc2[2][3], a2v, b3);
            FMA2(acc2[3][0], a3, b0); FMA2(acc2[3][1], a3, b1);
            FMA2(acc2[3][2], a3, b2); FMA2(acc2[3][3], a3, b3);
        }
        __syncthreads();

        bool diag = (tt == qt);
        #pragma unroll
        for (int ip = 0; ip < 4; ip++) {
            #pragma unroll
            for (int half = 0; half < 2; half++) {
                int r = ip * 2 + half;
                int q = q0 + ty * 8 + r;
                bool vrow = (q >= p);
                int tb = t0 + tx * 4;
                float x0 = half ? hi2(acc2[ip][0]) : lo2(acc2[ip][0]);
                float x1 = half ? hi2(acc2[ip][1]) : lo2(acc2[ip][1]);
                float x2 = half ? hi2(acc2[ip][2]) : lo2(acc2[ip][2]);
                float x3 = half ? hi2(acc2[ip][3]) : lo2(acc2[ip][3]);
                float4 v;
                v.x = (vrow && (!diag || tb + 0 <= q)) ? __expf(x0 * 0.015625f) : 0.0f;
                v.y = (vrow && (!diag || tb + 1 <= q)) ? __expf(x1 * 0.015625f) : 0.0f;
                v.z = (vrow && (!diag || tb + 2 <= q)) ? __expf(x2 * 0.015625f) : 0.0f;
                v.w = (vrow && (!diag || tb + 3 <= q)) ? __expf(x3 * 0.015625f) : 0.0f;
                srow[r] += (v.x + v.y) + (v.z + v.w);
                *reinterpret_cast<float4*>(&Cb[(long long)q * T + tb]) = v;
            }
        }
    }

    // reduce srow across the 16-lane tx group, lane tx==0 writes partial
    #pragma unroll
    for (int r = 0; r < 8; r++) {
        float s = srow[r];
        s += __shfl_xor_sync(0xffffffffu, s, 1);
        s += __shfl_xor_sync(0xffffffffu, s, 2);
        s += __shfl_xor_sync(0xffffffffu, s, 4);
        s += __shfl_xor_sync(0xffffffffu, s, 8);
        if (tx == 0)
            s_part[((long long)(h * T + p)) * T + q0 + ty * 8 + r] = s;
    }
}

// ---------------------------------------------------------------------------
// rowinv[h,q] = 1 / sum_{p<=q} s_part[h][p][q]
// ---------------------------------------------------------------------------
__global__ void rowinv_kernel(const float* __restrict__ s_part,
                              float* __restrict__ rowinv)
{
    int q = blockIdx.x, h = blockIdx.y;
    int tid = threadIdx.x;    // 256, tid == p
    float s = (tid <= q) ? s_part[((long long)(h * T + tid)) * T + q] : 0.0f;
    __shared__ float sh[256];
    sh[tid] = s;
    __syncthreads();
    for (int o = 128; o > 0; o >>= 1) {
        if (tid < o) sh[tid] += sh[tid + o];
        __syncthreads();
    }
    if (tid == 0) rowinv[h * T + q] = 1.0f / sh[0];
}

// ---------------------------------------------------------------------------
static inline void launch_gemm(const float* A, long long aH, long long aP, int lda,
                               const float* B, long long bH, long long bP, int ldb,
                               float* C, long long cH, long long cP, int ldc,
                               int M, int N, int K, int P, int batch,
                               int transB, const float* bias,
                               const float* rowscale, int rsH,
                               int mode, int ksplit)
{
    dim3 grid(N / 64, M / 64, batch * ksplit);
    gemm_kernel<<<grid, 128>>>(A, B, C, lda, ldb, ldc, M, N, K, P,
                               aH, aP, bH, bP, cH, cP,
                               transB, bias, rowscale, rsH, mode, ksplit);
}

extern "C" void kernel_launch(void* const* d_in, const int* in_sizes, int n_in,
                              void* d_out, int out_size)
{
    const float* x    = (const float*)d_in[0];   // [256, 512]
    const float* Wk   = (const float*)d_in[1];   // [512, 2560]
    const float* bk   = (const float*)d_in[2];   // [2560]
    const float* WKq  = (const float*)d_in[3];   // [8,64,64,64]
    const float* WVq  = (const float*)d_in[4];   // [8,64,64,64]
    const float* Wout = (const float*)d_in[5];   // [512, 512]
    const float* bout = (const float*)d_in[6];   // [512]
    float* out = (float*)d_out;                  // [256, 512]

    float *proj, *k1w, *vq1, *attn, *A2, *spart, *rinv, *z;
    cudaGetSymbolAddress((void**)&proj,  g_proj);
    cudaGetSymbolAddress((void**)&k1w,   g_K1W);
    cudaGetSymbolAddress((void**)&vq1,   g_Vq1);
    cudaGetSymbolAddress((void**)&attn,  g_attn);
    cudaGetSymbolAddress((void**)&A2,    g_A2);
    cudaGetSymbolAddress((void**)&spart, g_spart);
    cudaGetSymbolAddress((void**)&rinv,  g_rowinv);
    cudaGetSymbolAddress((void**)&z,     g_z);

    const long long HPJ = (long long)T * DH * DH;
    const long long SH  = (long long)T * T * DH;
    const long long AH  = (long long)T * T * T;

    // 1) proj = x @ W_kkqvv + b
    launch_gemm(x, 0, 0, D, Wk, 0, 0, 5 * D, proj, 0, 0, 5 * D,
                T, 5 * D, D, 1, 1, 0, bk, nullptr, 0, 0, 1);

    // 2) K1W[h] = k1_h @ W_Kq[h]
    launch_gemm(proj + 0, 64, 0, 5 * D, WKq, (long long)DH * DH * DH, 0, DH * DH,
                k1w, HPJ, 0, DH * DH,
                T, DH * DH, DH, 1, H, 0, nullptr, nullptr, 0, 0, 1);

    // 3) Vq1[h] = v1_h @ W_Vq[h]
    launch_gemm(proj + 3 * D, 64, 0, 5 * D, WVq, (long long)DH * DH * DH, 0, DH * DH,
                vq1, HPJ, 0, DH * DH,
                T, DH * DH, DH, 1, H, 0, nullptr, nullptr, 0, 0, 1);

    // 4+5+exp fused) attn weights + partial row sums
    {
        dim3 grid(T / 64, T, H);
        logits_kernel<<<grid, 128>>>(proj, k1w, attn, spart);
    }

    // 6) rowinv
    {
        dim3 grid(T, H);
        rowinv_kernel<<<grid, 256>>>(spart, rinv);
    }

    // 7) A2[h][q][p*64+c] = rowinv[h,q] * sum_t e[p][q][t] * v2_h[t,c]  (pure GEMM)
    launch_gemm(attn, AH, (long long)T * T, T,
                proj + 4 * D, 64, 0, 5 * D,
                A2, SH, DH, T * DH,
                T, DH, T, T, H * T, 0, nullptr, rinv, T, 2, 1);

    // 8) z[q][h*64+e] = sum_{p,c} A2[h][q][p*64+c] * Vq1[h][(p*64+c)][e]
    cudaMemsetAsync(z, 0, (size_t)T * H * DH * sizeof(float));
    launch_gemm(A2, SH, 0, T * DH,
                vq1, HPJ, 0, DH,
                z, DH, 0, H * DH,
                T, DH, T * DH, 1, H, 0, nullptr, nullptr, 0, 0, 16);

    // 9) out = z @ W_out + b_out
    launch_gemm(z, 0, 0, H * DH, Wout, 0, 0, D,
                out, 0, 0, D,
                T, D, H * DH, 1, 1, 0, bout, nullptr, 0, 0, 1);
}

// round 6
// speedup vs baseline: 2.4852x; 1.0842x over previous
#include <cuda_runtime.h>
#include <cstdint>

// ---------------------------------------------------------------------------
// Problem constants: B=1, T=256, D=512, H=8, DH=64
// proj layout: [t, 5*512]; chunks k1@0, k2@512, q@1024, v1@1536, v2@2048.
// ---------------------------------------------------------------------------
#define T 256
#define D 512
#define H 8
#define DH 64
#define SST 66   // smem row stride (floats), even for 64-bit LDS

// Packed fp32x2 FMA (sm_100+)
#define FMA2(acc, a, b) asm("fma.rn.f32x2 %0, %1, %2, %0;" : "+l"(acc) : "l"(a), "l"(b))
#define DUP2(dst, f)    asm("mov.b64 %0, {%1, %1};" : "=l"(dst) : "r"(__float_as_uint(f)))
static __device__ __forceinline__ float lo2(unsigned long long v) { return __uint_as_float((unsigned int)v); }
static __device__ __forceinline__ float hi2(unsigned long long v) { return __uint_as_float((unsigned int)(v >> 32)); }

// 16x FFMA2 rank-1 update block: acc[4][4] += apair[4] x bdup[4]
#define RANK1_FMA2(ACC, AR, B0, B1, B2, B3)                         \
    do {                                                            \
        unsigned long long _a0 = (AR)[0], _a1 = (AR)[1];            \
        unsigned long long _a2 = (AR)[2], _a3 = (AR)[3];            \
        FMA2(ACC[0][0], _a0, B0); FMA2(ACC[0][1], _a0, B1);         \
        FMA2(ACC[0][2], _a0, B2); FMA2(ACC[0][3], _a0, B3);         \
        FMA2(ACC[1][0], _a1, B0); FMA2(ACC[1][1], _a1, B1);         \
        FMA2(ACC[1][2], _a1, B2); FMA2(ACC[1][3], _a1, B3);         \
        FMA2(ACC[2][0], _a2, B0); FMA2(ACC[2][1], _a2, B1);         \
        FMA2(ACC[2][2], _a2, B2); FMA2(ACC[2][3], _a2, B3);         \
        FMA2(ACC[3][0], _a3, B0); FMA2(ACC[3][1], _a3, B1);         \
        FMA2(ACC[3][2], _a3, B2); FMA2(ACC[3][3], _a3, B3);         \
    } while (0)

// Scratch (device globals — allocation-free rule)
__device__ float g_proj[T * 5 * D];
__device__ float g_K1W[H * T * DH * DH];
__device__ float g_Vq1[H * T * DH * DH];
__device__ float g_A2[H * T * T * DH];   // [h][q][p*64+c], unscaled
__device__ float g_spart[H * T * T];     // [h][p][q]
__device__ float g_rowinv[H * T];
__device__ float g_z[T * H * DH];

// ---------------------------------------------------------------------------
// Generic batched tiled GEMM, 64x64 tile, 128 threads, 8x4/thread, FFMA2.
//   C[m,n] = sum_k A[m,k] * B(k,n); batch b -> h=b/P, p=b%P
//   transB: B indexed [n*ldb + k]
//   mode 4 (z step): k_end = min(K, (m0+64)*64); early-exit empty chunks.
//   ksplit>1: split-K with atomicAdd epilogue; rowscale: per-row scale.
// ---------------------------------------------------------------------------
__global__ __launch_bounds__(128)
void gemm_kernel(const float* __restrict__ A, const float* __restrict__ Bm,
                 float* __restrict__ C,
                 int lda, int ldb, int ldc,
                 int M, int N, int K, int P,
                 long long aH, long long aP,
                 long long bH, long long bP,
                 long long cH, long long cP,
                 int transB,
                 const float* __restrict__ bias,
                 const float* __restrict__ rowscale, int rsH,
                 int mode, int ksplit)
{
    int bz = blockIdx.z;
    int b  = bz / ksplit;
    int kc = bz % ksplit;
    int h = b / P, p = b % P;
    A  += (long long)h * aH + (long long)p * aP;
    Bm += (long long)h * bH + (long long)p * bP;
    C  += (long long)h * cH + (long long)p * cP;

    int m0 = blockIdx.y * 64;
    int n0 = blockIdx.x * 64;

    int k_begin = 0, k_end = K;
    if (ksplit > 1) { int kchunk = K / ksplit; k_begin = kc * kchunk; k_end = k_begin + kchunk; }
    if (mode == 4) {
        long long lim = (long long)(m0 + 64) * 64;
        if (lim < k_end) k_end = (int)lim;
        if (k_begin >= k_end) return;   // atomic path: no contribution
    }

    __shared__ float As[64][SST];
    __shared__ float Bs[64][SST];

    int tid = threadIdx.x;
    int ty = tid >> 4, tx = tid & 15;

    unsigned long long acc2[4][4];
    #pragma unroll
    for (int i = 0; i < 4; i++)
        #pragma unroll
        for (int j = 0; j < 4; j++) acc2[i][j] = 0ULL;

    for (int k0 = k_begin; k0 < k_end; k0 += 64) {
        #pragma unroll 8
        for (int i = tid; i < 4096; i += 128) {
            int r = i >> 6, kk = i & 63;
            As[kk][r] = A[(long long)(m0 + r) * lda + (k0 + kk)];
        }
        if (transB) {
            #pragma unroll 8
            for (int i = tid; i < 4096; i += 128) {
                int n = i >> 6, kk = i & 63;
                Bs[kk][n] = Bm[(long long)(n0 + n) * ldb + (k0 + kk)];
            }
        } else {
            #pragma unroll 8
            for (int i = tid; i < 4096; i += 128) {
                int kk = i >> 6, n = i & 63;
                Bs[kk][n] = Bm[(long long)(k0 + kk) * ldb + (n0 + n)];
            }
        }
        __syncthreads();

        #pragma unroll 16
        for (int kk = 0; kk < 64; kk++) {
            const unsigned long long* arow =
                reinterpret_cast<const unsigned long long*>(&As[kk][ty * 8]);
            unsigned long long b0, b1, b2, b3;
            DUP2(b0, Bs[kk][tx * 4 + 0]); DUP2(b1, Bs[kk][tx * 4 + 1]);
            DUP2(b2, Bs[kk][tx * 4 + 2]); DUP2(b3, Bs[kk][tx * 4 + 3]);
            RANK1_FMA2(acc2, arow, b0, b1, b2, b3);
        }
        __syncthreads();
    }

    int n = n0 + tx * 4;
    float4 bv4 = {0,0,0,0};
    if (bias) { bv4.x = bias[n]; bv4.y = bias[n+1]; bv4.z = bias[n+2]; bv4.w = bias[n+3]; }
    #pragma unroll
    for (int ip = 0; ip < 4; ip++) {
        #pragma unroll
        for (int half = 0; half < 2; half++) {
            int m = m0 + ty * 8 + ip * 2 + half;
            float scale = rowscale ? rowscale[h * rsH + m] : 1.0f;
            float4 v;
            v.x = (half ? hi2(acc2[ip][0]) : lo2(acc2[ip][0])) * scale + bv4.x;
            v.y = (half ? hi2(acc2[ip][1]) : lo2(acc2[ip][1])) * scale + bv4.y;
            v.z = (half ? hi2(acc2[ip][2]) : lo2(acc2[ip][2])) * scale + bv4.z;
            v.w = (half ? hi2(acc2[ip][3]) : lo2(acc2[ip][3])) * scale + bv4.w;
            if (ksplit > 1) {
                atomicAdd(&C[(long long)m * ldc + n + 0], v.x);
                atomicAdd(&C[(long long)m * ldc + n + 1], v.y);
                atomicAdd(&C[(long long)m * ldc + n + 2], v.z);
                atomicAdd(&C[(long long)m * ldc + n + 3], v.w);
            } else {
                *reinterpret_cast<float4*>(&C[(long long)m * ldc + n]) = v;
            }
        }
    }
}

// ---------------------------------------------------------------------------
// Fully fused attention inner: per (h, p, qtile):
//   Phase1: St[j][q] = sum_i q_h[q,i] * K1W[h][p][j*64+i]
//   Per t-tile tt <= qt:
//     e[q][t] = (q>=p && t<=q) ? exp(logit/64) : 0      (regs)
//     Es[t][q] = e  (smem transpose);  srow[q] += sum_t e
//     A2acc[q][c] += sum_t Es[t][q] * v2[t0+t][c]
//   Epilogue: A2[h][q][p*64+c] = A2acc (unscaled), s_part[h][p][q] = srow
// grid = (qt=4, p=256, h=8), block = 128, dynamic smem 4*64*SST floats.
// ---------------------------------------------------------------------------
__global__ __launch_bounds__(128)
void attn_kernel(const float* __restrict__ proj,
                 const float* __restrict__ k1w,
                 float* __restrict__ A2,
                 float* __restrict__ s_part)
{
    int qt = blockIdx.x;
    int p  = blockIdx.y;
    int h  = blockIdx.z;
    if (qt * 64 + 63 < p) return;

    extern __shared__ float sm_dyn[];
    float* As = sm_dyn;                  // phase1 [i][q]; then St[j][q]
    float* Bs = sm_dyn + 64 * SST;       // phase1 [i][j]; phase2 k2 [j][t]
    float* Es = sm_dyn + 2 * 64 * SST;   // e transposed [t][q]
    float* Vs = sm_dyn + 3 * 64 * SST;   // v2 tile [t][c]

    const float* qmat = proj + 2 * D + h * 64;           // [q][i], ld=5D
    const float* k2m  = proj + 1 * D + h * 64;           // [t][j], ld=5D
    const float* v2m  = proj + 4 * D + h * 64;           // [t][c], ld=5D
    const float* Bp   = k1w + ((long long)h * T + p) * (DH * DH);

    int tid = threadIdx.x;
    int ty = tid >> 4, tx = tid & 15;
    int q0 = qt * 64;

    // ---- Phase 1: St[q][j] = sum_i q[q,i] * K1W[j*64+i] ----
    unsigned long long st2[4][4];
    #pragma unroll
    for (int i = 0; i < 4; i++)
        #pragma unroll
        for (int j = 0; j < 4; j++) st2[i][j] = 0ULL;

    #pragma unroll 8
    for (int i = tid; i < 4096; i += 128) {
        int r = i >> 6, kk = i & 63;
        As[kk * SST + r] = qmat[(long long)(q0 + r) * (5 * D) + kk];
    }
    #pragma unroll 8
    for (int i = tid; i < 4096; i += 128) {
        int j = i >> 6, ii = i & 63;
        Bs[ii * SST + j] = Bp[i];
    }
    __syncthreads();

    #pragma unroll 16
    for (int kk = 0; kk < 64; kk++) {
        const unsigned long long* arow =
            reinterpret_cast<const unsigned long long*>(&As[kk * SST + ty * 8]);
        unsigned long long b0, b1, b2, b3;
        DUP2(b0, Bs[kk * SST + tx * 4 + 0]); DUP2(b1, Bs[kk * SST + tx * 4 + 1]);
        DUP2(b2, Bs[kk * SST + tx * 4 + 2]); DUP2(b3, Bs[kk * SST + tx * 4 + 3]);
        RANK1_FMA2(st2, arow, b0, b1, b2, b3);
    }
    __syncthreads();

    // store St transposed into As: As[j][q]
    #pragma unroll
    for (int ip = 0; ip < 4; ip++)
        #pragma unroll
        for (int j = 0; j < 4; j++) {
            As[(tx * 4 + j) * SST + ty * 8 + ip * 2 + 0] = lo2(st2[ip][j]);
            As[(tx * 4 + j) * SST + ty * 8 + ip * 2 + 1] = hi2(st2[ip][j]);
        }

    float srow[8];
    #pragma unroll
    for (int r = 0; r < 8; r++) srow[r] = 0.0f;

    unsigned long long accA[4][4];       // A2 tile acc [qpair][c]
    #pragma unroll
    for (int i = 0; i < 4; i++)
        #pragma unroll
        for (int j = 0; j < 4; j++) accA[i][j] = 0ULL;

    // ---- Phase 2: t-tiles ----
    for (int tt = 0; tt <= qt; tt++) {
        int t0 = tt * 64;
        __syncthreads();   // prev GEMM2 done with Vs; St store visible (tt=0)

        #pragma unroll 8
        for (int i = tid; i < 4096; i += 128) {
            int t = i >> 6, jj = i & 63;
            Bs[jj * SST + t] = k2m[(long long)(t0 + t) * (5 * D) + jj];
        }
        #pragma unroll 8
        for (int i = tid; i < 4096; i += 128) {
            int t = i >> 6, c = i & 63;
            Vs[t * SST + c] = v2m[(long long)(t0 + t) * (5 * D) + c];
        }
        __syncthreads();

        // GEMM1: e = St^T x k2^T   (rows q, cols t, contract j)
        unsigned long long acc2[4][4];
        #pragma unroll
        for (int i = 0; i < 4; i++)
            #pragma unroll
            for (int j = 0; j < 4; j++) acc2[i][j] = 0ULL;

        #pragma unroll 16
        for (int kk = 0; kk < 64; kk++) {
            const unsigned long long* arow =
                reinterpret_cast<const unsigned long long*>(&As[kk * SST + ty * 8]);
            unsigned long long b0, b1, b2, b3;
            DUP2(b0, Bs[kk * SST + tx * 4 + 0]); DUP2(b1, Bs[kk * SST + tx * 4 + 1]);
            DUP2(b2, Bs[kk * SST + tx * 4 + 2]); DUP2(b3, Bs[kk * SST + tx * 4 + 3]);
            RANK1_FMA2(acc2, arow, b0, b1, b2, b3);
        }

        // exp + mask -> Es[t][q] (transposed store) + row sums
        bool diag = (tt == qt);
        #pragma unroll
        for (int ip = 0; ip < 4; ip++) {
            #pragma unroll
            for (int half = 0; half < 2; half++) {
                int r = ip * 2 + half;
                int q = q0 + ty * 8 + r;
                bool vrow = (q >= p);
                int tb = t0 + tx * 4;
                float x0 = half ? hi2(acc2[ip][0]) : lo2(acc2[ip][0]);
                float x1 = half ? hi2(acc2[ip][1]) : lo2(acc2[ip][1]);
                float x2 = half ? hi2(acc2[ip][2]) : lo2(acc2[ip][2]);
                float x3 = half ? hi2(acc2[ip][3]) : lo2(acc2[ip][3]);
                float e0 = (vrow && (!diag || tb + 0 <= q)) ? __expf(x0 * 0.015625f) : 0.0f;
                float e1 = (vrow && (!diag || tb + 1 <= q)) ? __expf(x1 * 0.015625f) : 0.0f;
                float e2 = (vrow && (!diag || tb + 2 <= q)) ? __expf(x2 * 0.015625f) : 0.0f;
                float e3 = (vrow && (!diag || tb + 3 <= q)) ? __expf(x3 * 0.015625f) : 0.0f;
                srow[r] += (e0 + e1) + (e2 + e3);
                int qc = ty * 8 + r;
                Es[(tx * 4 + 0) * SST + qc] = e0;
                Es[(tx * 4 + 1) * SST + qc] = e1;
                Es[(tx * 4 + 2) * SST + qc] = e2;
                Es[(tx * 4 + 3) * SST + qc] = e3;
            }
        }
        __syncthreads();

        // GEMM2: A2acc[q][c] += Es[t][q] * Vs[t][c]   (contract t)
        #pragma unroll 16
        for (int kk = 0; kk < 64; kk++) {
            const unsigned long long* arow =
                reinterpret_cast<const unsigned long long*>(&Es[kk * SST + ty * 8]);
            unsigned long long b0, b1, b2, b3;
            DUP2(b0, Vs[kk * SST + tx * 4 + 0]); DUP2(b1, Vs[kk * SST + tx * 4 + 1]);
            DUP2(b2, Vs[kk * SST + tx * 4 + 2]); DUP2(b3, Vs[kk * SST + tx * 4 + 3]);
            RANK1_FMA2(accA, arow, b0, b1, b2, b3);
        }
    }

    // ---- Epilogue: A2 tile + s_part ----
    #pragma unroll
    for (int ip = 0; ip < 4; ip++) {
        #pragma unroll
        for (int half = 0; half < 2; half++) {
            int q = q0 + ty * 8 + ip * 2 + half;
            float4 v;
            v.x = half ? hi2(accA[ip][0]) : lo2(accA[ip][0]);
            v.y = half ? hi2(accA[ip][1]) : lo2(accA[ip][1]);
            v.z = half ? hi2(accA[ip][2]) : lo2(accA[ip][2]);
            v.w = half ? hi2(accA[ip][3]) : lo2(accA[ip][3]);
            *reinterpret_cast<float4*>(
                &A2[((long long)(h * T + q)) * (T * DH) + p * 64 + tx * 4]) = v;
        }
    }

    #pragma unroll
    for (int r = 0; r < 8; r++) {
        float s = srow[r];
        s += __shfl_xor_sync(0xffffffffu, s, 1);
        s += __shfl_xor_sync(0xffffffffu, s, 2);
        s += __shfl_xor_sync(0xffffffffu, s, 4);
        s += __shfl_xor_sync(0xffffffffu, s, 8);
        if (tx == 0)
            s_part[((long long)(h * T + p)) * T + q0 + ty * 8 + r] = s;
    }
}

// ---------------------------------------------------------------------------
// rowinv[h,q] = 1 / sum_{p<=q} s_part[h][p][q]
// ---------------------------------------------------------------------------
__global__ void rowinv_kernel(const float* __restrict__ s_part,
                              float* __restrict__ rowinv)
{
    int q = blockIdx.x, h = blockIdx.y;
    int tid = threadIdx.x;    // 256, tid == p
    float s = (tid <= q) ? s_part[((long long)(h * T + tid)) * T + q] : 0.0f;
    __shared__ float sh[256];
    sh[tid] = s;
    __syncthreads();
    for (int o = 128; o > 0; o >>= 1) {
        if (tid < o) sh[tid] += sh[tid + o];
        __syncthreads();
    }
    if (tid == 0) rowinv[h * T + q] = 1.0f / sh[0];
}

// ---------------------------------------------------------------------------
static inline void launch_gemm(const float* A, long long aH, long long aP, int lda,
                               const float* B, long long bH, long long bP, int ldb,
                               float* C, long long cH, long long cP, int ldc,
                               int M, int N, int K, int P, int batch,
                               int transB, const float* bias,
                               const float* rowscale, int rsH,
                               int mode, int ksplit)
{
    dim3 grid(N / 64, M / 64, batch * ksplit);
    gemm_kernel<<<grid, 128>>>(A, B, C, lda, ldb, ldc, M, N, K, P,
                               aH, aP, bH, bP, cH, cP,
                               transB, bias, rowscale, rsH, mode, ksplit);
}

extern "C" void kernel_launch(void* const* d_in, const int* in_sizes, int n_in,
                              void* d_out, int out_size)
{
    const float* x    = (const float*)d_in[0];
    const float* Wk   = (const float*)d_in[1];
    const float* bk   = (const float*)d_in[2];
    const float* WKq  = (const float*)d_in[3];
    const float* WVq  = (const float*)d_in[4];
    const float* Wout = (const float*)d_in[5];
    const float* bout = (const float*)d_in[6];
    float* out = (float*)d_out;

    float *proj, *k1w, *vq1, *A2, *spart, *rinv, *z;
    cudaGetSymbolAddress((void**)&proj,  g_proj);
    cudaGetSymbolAddress((void**)&k1w,   g_K1W);
    cudaGetSymbolAddress((void**)&vq1,   g_Vq1);
    cudaGetSymbolAddress((void**)&A2,    g_A2);
    cudaGetSymbolAddress((void**)&spart, g_spart);
    cudaGetSymbolAddress((void**)&rinv,  g_rowinv);
    cudaGetSymbolAddress((void**)&z,     g_z);

    const long long HPJ = (long long)T * DH * DH;
    const long long A2H = (long long)T * T * DH;

    // 1) proj = x @ W_kkqvv + b
    launch_gemm(x, 0, 0, D, Wk, 0, 0, 5 * D, proj, 0, 0, 5 * D,
                T, 5 * D, D, 1, 1, 0, bk, nullptr, 0, 0, 1);

    // 2) K1W[h] = k1_h @ W_Kq[h]
    launch_gemm(proj + 0, 64, 0, 5 * D, WKq, (long long)DH * DH * DH, 0, DH * DH,
                k1w, HPJ, 0, DH * DH,
                T, DH * DH, DH, 1, H, 0, nullptr, nullptr, 0, 0, 1);

    // 3) Vq1[h] = v1_h @ W_Vq[h]
    launch_gemm(proj + 3 * D, 64, 0, 5 * D, WVq, (long long)DH * DH * DH, 0, DH * DH,
                vq1, HPJ, 0, DH * DH,
                T, DH * DH, DH, 1, H, 0, nullptr, nullptr, 0, 0, 1);

    // 4) fused attention inner: A2 (unscaled) + partial row sums
    {
        int smem_bytes = 4 * 64 * SST * sizeof(float);   // 67584
        cudaFuncSetAttribute(attn_kernel,
                             cudaFuncAttributeMaxDynamicSharedMemorySize, smem_bytes);
        dim3 grid(T / 64, T, H);
        attn_kernel<<<grid, 128, smem_bytes>>>(proj, k1w, A2, spart);
    }

    // 5) rowinv
    {
        dim3 grid(T, H);
        rowinv_kernel<<<grid, 256>>>(spart, rinv);
    }

    // 6) z[q][h*64+e] = rinv[h,q] * sum_{p,c} A2[h][q][p*64+c] * Vq1[h][(p*64+c)][e]
    cudaMemsetAsync(z, 0, (size_t)T * H * DH * sizeof(float));
    launch_gemm(A2, A2H, 0, T * DH,
                vq1, HPJ, 0, DH,
                z, DH, 0, H * DH,
                T, DH, T * DH, 1, H, 0, nullptr, rinv, T, 4, 16);

    // 7) out = z @ W_out + b_out
    launch_gemm(z, 0, 0, H * DH, Wout, 0, 0, D,
                out, 0, 0, D,
                T, D, H * DH, 1, 1, 0, bout, nullptr, 0, 0, 1);
}